// round 14
// baseline (speedup 1.0000x reference)
#include <cuda_runtime.h>
#include <cuda_bf16.h>
#include <math.h>
#include <stdint.h>

#define N_ENT 1024
#define BATCH 128
#define T_TOK 64
#define P_TOK 49
#define D_IN 768
#define H_DIM 512
#define N_EXP 8
#define NKP (D_IN / 2)
#define WSP_SZ (NKP * H_DIM)

// ----------------------------- static scratch ------------------------------
__device__ float g_etc[N_ENT * H_DIM];
__device__ float g_eic[N_ENT * H_DIM];
__device__ float g_mtc[BATCH * H_DIM];
__device__ float g_mic[BATCH * H_DIM];
__device__ float g_ett[N_ENT * T_TOK * H_DIM];
__device__ float g_eit[N_ENT * P_TOK * H_DIM];
__device__ float g_mtt[BATCH * T_TOK * H_DIM];
__device__ float g_mit[BATCH * P_TOK * H_DIM];

__device__ float g_eti_m[N_ENT * 50 * H_DIM];
__device__ float g_mti_m[BATCH * 50 * H_DIM];
__device__ float g_eit_m[N_ENT * 65 * H_DIM];
__device__ float g_mit_m[BATCH * 65 * H_DIM];

__device__ int2   g_eidx[4][N_ENT];
__device__ float2 g_ew[4][N_ENT];

__device__ float g_ctx0[N_ENT * H_DIM];
__device__ float g_ctx1[BATCH * H_DIM];
__device__ float g_ctx2[N_ENT * H_DIM];
__device__ float g_ctx3[BATCH * H_DIM];

__device__ float g_fe_ti[N_ENT * H_DIM];
__device__ float g_fm_ti[BATCH * H_DIM];
__device__ float g_fe_it[N_ENT * H_DIM];
__device__ float g_fm_it[BATCH * H_DIM];

__device__ float g_wc_text[D_IN * N_EXP];
__device__ float g_wc_img[D_IN * N_EXP];
__device__ float g_bterm[2 * N_EXP];

// pre-split projection weights: packed bf16 pairs (k, k+1), [pair][n]
__device__ uint32_t g_wsp_h[2 * WSP_SZ];
__device__ uint32_t g_wsp_l[2 * WSP_SZ];

// --------------------------- bf16 split helpers -----------------------------
__device__ __forceinline__ void split_bf16x2(float a, float b, uint32_t& h, uint32_t& l)
{
    __nv_bfloat162 hp = __floats2bfloat162_rn(a, b);
    float ra = a - __bfloat162float(hp.x);
    float rb = b - __bfloat162float(hp.y);
    __nv_bfloat162 lp = __floats2bfloat162_rn(ra, rb);
    h = *(uint32_t*)&hp;
    l = *(uint32_t*)&lp;
}

__device__ __forceinline__ void splitB4(float4 r0, float4 r1, uint4& h, uint4& l)
{
    split_bf16x2(r0.x, r1.x, h.x, l.x);
    split_bf16x2(r0.y, r1.y, h.y, l.y);
    split_bf16x2(r0.z, r1.z, h.z, l.z);
    split_bf16x2(r0.w, r1.w, h.w, l.w);
}

__device__ __forceinline__ void mma16(float* c, const uint32_t* a, const uint32_t* b)
{
    asm volatile(
        "mma.sync.aligned.m16n8k16.row.col.f32.bf16.bf16.f32 "
        "{%0,%1,%2,%3}, {%4,%5,%6,%7}, {%8,%9}, {%0,%1,%2,%3};"
        : "+f"(c[0]), "+f"(c[1]), "+f"(c[2]), "+f"(c[3])
        : "r"(a[0]), "r"(a[1]), "r"(a[2]), "r"(a[3]), "r"(b[0]), "r"(b[1]));
}

#define ASTRP 12
#define BSTRP 136
#define BSTRP2 264

// ----------------- proj (bf16x3): C[M,512]=A[M,768]@W+bias -----------------
// grid (4 col-tiles, M/128 row-tiles); W pre-split packed pairs. 3 CTAs/SM.
__global__ __launch_bounds__(128, 3) void proj_tc(
    const float* __restrict__ A,
    const uint32_t* __restrict__ Wh, const uint32_t* __restrict__ Wl,
    const float* __restrict__ bias, float* __restrict__ C, int M)
{
    __shared__ uint32_t AsH[128 * ASTRP], AsL[128 * ASTRP];
    __shared__ uint32_t BsH[8 * BSTRP], BsL[8 * BSTRP];

    const int tid = threadIdx.x;
    const int row0 = blockIdx.y * 128;
    const int col0 = blockIdx.x * 128;
    const int warp = tid >> 5, lane = tid & 31;
    const int wm = warp >> 1, wn = warp & 1;
    const int gid = lane >> 2, tig = lane & 3;
    const int bk = tid >> 4;
    const int nc = (tid & 15) * 8;

    float acc[4][8][4];
#pragma unroll
    for (int a = 0; a < 4; a++)
#pragma unroll
        for (int b = 0; b < 8; b++)
#pragma unroll
            for (int c = 0; c < 4; c++) acc[a][b][c] = 0.f;

    const float* Arow = A + (size_t)(row0 + tid) * D_IN;

    for (int kb = 0; kb < D_IN / 16; kb++) {
        const int k0 = kb * 16;
#pragma unroll
        for (int q = 0; q < 4; q++) {
            float4 v = *(const float4*)(Arow + k0 + q * 4);
            uint32_t h0, l0, h1, l1;
            split_bf16x2(v.x, v.y, h0, l0);
            split_bf16x2(v.z, v.w, h1, l1);
            *(uint2*)&AsH[tid * ASTRP + q * 2] = make_uint2(h0, h1);
            *(uint2*)&AsL[tid * ASTRP + q * 2] = make_uint2(l0, l1);
        }
        {
            size_t off = (size_t)(kb * 8 + bk) * H_DIM + col0 + nc;
            *(uint4*)&BsH[bk * BSTRP + nc]     = *(const uint4*)(Wh + off);
            *(uint4*)&BsH[bk * BSTRP + nc + 4] = *(const uint4*)(Wh + off + 4);
            *(uint4*)&BsL[bk * BSTRP + nc]     = *(const uint4*)(Wl + off);
            *(uint4*)&BsL[bk * BSTRP + nc + 4] = *(const uint4*)(Wl + off + 4);
        }
        __syncthreads();

        uint32_t ah[4][4], al[4][4], bh[8][2], bl[8][2];
#pragma unroll
        for (int mt = 0; mt < 4; mt++) {
            int r = (wm * 64 + mt * 16 + gid) * ASTRP;
            ah[mt][0] = AsH[r + tig];     ah[mt][1] = AsH[r + 8 * ASTRP + tig];
            ah[mt][2] = AsH[r + tig + 4]; ah[mt][3] = AsH[r + 8 * ASTRP + tig + 4];
            al[mt][0] = AsL[r + tig];     al[mt][1] = AsL[r + 8 * ASTRP + tig];
            al[mt][2] = AsL[r + tig + 4]; al[mt][3] = AsL[r + 8 * ASTRP + tig + 4];
        }
#pragma unroll
        for (int nt = 0; nt < 8; nt++) {
            int c = wn * 64 + nt * 8 + gid;
            bh[nt][0] = BsH[tig * BSTRP + c]; bh[nt][1] = BsH[(tig + 4) * BSTRP + c];
            bl[nt][0] = BsL[tig * BSTRP + c]; bl[nt][1] = BsL[(tig + 4) * BSTRP + c];
        }
#pragma unroll
        for (int mt = 0; mt < 4; mt++)
#pragma unroll
            for (int nt = 0; nt < 8; nt++) mma16(acc[mt][nt], ah[mt], bh[nt]);
#pragma unroll
        for (int mt = 0; mt < 4; mt++)
#pragma unroll
            for (int nt = 0; nt < 8; nt++) mma16(acc[mt][nt], ah[mt], bl[nt]);
#pragma unroll
        for (int mt = 0; mt < 4; mt++)
#pragma unroll
            for (int nt = 0; nt < 8; nt++) mma16(acc[mt][nt], al[mt], bh[nt]);
        __syncthreads();
    }

#pragma unroll
    for (int mt = 0; mt < 4; mt++) {
        int m = row0 + wm * 64 + mt * 16 + gid;
#pragma unroll
        for (int nt = 0; nt < 8; nt++) {
            int n = col0 + wn * 64 + nt * 8 + tig * 2;
            float2 bv = *(const float2*)(bias + n);
            *(float2*)(C + (size_t)m * H_DIM + n) =
                make_float2(acc[mt][nt][0] + bv.x, acc[mt][nt][1] + bv.y);
            *(float2*)(C + (size_t)(m + 8) * H_DIM + n) =
                make_float2(acc[mt][nt][2] + bv.x, acc[mt][nt][3] + bv.y);
        }
    }
}

// -------- MoE S=50 (bf16x3): block 64x256, 4 warps of 64x64, 3 CTAs/SM -----
__global__ __launch_bounds__(128, 3) void moe2_tc(
    const float* __restrict__ cls, const float* __restrict__ tok,
    const float* __restrict__ We, const float* __restrict__ be,
    const int2* __restrict__ eidx, const float2* __restrict__ ew,
    float* __restrict__ out)
{
    const int S = 50;
    __shared__ uint32_t AsH[64 * ASTRP], AsL[64 * ASTRP];
    __shared__ uint32_t BsH[8 * BSTRP2], BsL[8 * BSTRP2];

    const int i = blockIdx.z;
    const int col0 = blockIdx.x * 256;
    const int2 e = eidx[i];
    const float2 w = ew[i];
    const float* W0 = We + (size_t)e.x * H_DIM * H_DIM;
    const float* W1 = We + (size_t)e.y * H_DIM * H_DIM;

    const int tid = threadIdx.x;
    const int warp = tid >> 5, lane = tid & 31;
    const int wn = warp;
    const int gid = lane >> 2, tig = lane & 3;
    const int bk = tid >> 4;
    const int nc = (tid & 15) * 16;
    const int arow = tid & 63, ahalf = tid >> 6;

    const float* rp = nullptr;
    if (arow < S)
        rp = (arow == 0) ? (cls + (size_t)i * H_DIM)
                         : (tok + ((size_t)i * (S - 1) + (arow - 1)) * H_DIM);

    float acc[4][8][4];
#pragma unroll
    for (int a = 0; a < 4; a++)
#pragma unroll
        for (int b = 0; b < 8; b++)
#pragma unroll
            for (int c = 0; c < 4; c++) acc[a][b][c] = 0.f;

    for (int kb = 0; kb < H_DIM / 16; kb++) {
        const int k0 = kb * 16;
#pragma unroll
        for (int q = 0; q < 2; q++) {
            float4 v = make_float4(0.f, 0.f, 0.f, 0.f);
            if (rp) v = *(const float4*)(rp + k0 + ahalf * 8 + q * 4);
            uint32_t h0, l0, h1, l1;
            split_bf16x2(v.x, v.y, h0, l0);
            split_bf16x2(v.z, v.w, h1, l1);
            *(uint2*)&AsH[arow * ASTRP + ahalf * 4 + q * 2] = make_uint2(h0, h1);
            *(uint2*)&AsL[arow * ASTRP + ahalf * 4 + q * 2] = make_uint2(l0, l1);
        }
        {
            size_t o0 = (size_t)(k0 + 2 * bk) * H_DIM + col0 + nc;
#pragma unroll
            for (int q = 0; q < 4; q++) {
                float4 a0 = *(const float4*)(W0 + o0 + q * 4);
                float4 b0 = *(const float4*)(W1 + o0 + q * 4);
                float4 a1 = *(const float4*)(W0 + o0 + H_DIM + q * 4);
                float4 b1 = *(const float4*)(W1 + o0 + H_DIM + q * 4);
                float4 r0 = make_float4(w.x * a0.x + w.y * b0.x, w.x * a0.y + w.y * b0.y,
                                        w.x * a0.z + w.y * b0.z, w.x * a0.w + w.y * b0.w);
                float4 r1 = make_float4(w.x * a1.x + w.y * b1.x, w.x * a1.y + w.y * b1.y,
                                        w.x * a1.z + w.y * b1.z, w.x * a1.w + w.y * b1.w);
                uint4 h, l;
                splitB4(r0, r1, h, l);
                *(uint4*)&BsH[bk * BSTRP2 + nc + q * 4] = h;
                *(uint4*)&BsL[bk * BSTRP2 + nc + q * 4] = l;
            }
        }
        __syncthreads();

        uint32_t ah[4][4], al[4][4], bh[8][2], bl[8][2];
#pragma unroll
        for (int mt = 0; mt < 4; mt++) {
            int r = (mt * 16 + gid) * ASTRP;
            ah[mt][0] = AsH[r + tig];     ah[mt][1] = AsH[r + 8 * ASTRP + tig];
            ah[mt][2] = AsH[r + tig + 4]; ah[mt][3] = AsH[r + 8 * ASTRP + tig + 4];
            al[mt][0] = AsL[r + tig];     al[mt][1] = AsL[r + 8 * ASTRP + tig];
            al[mt][2] = AsL[r + tig + 4]; al[mt][3] = AsL[r + 8 * ASTRP + tig + 4];
        }
#pragma unroll
        for (int nt = 0; nt < 8; nt++) {
            int c = wn * 64 + nt * 8 + gid;
            bh[nt][0] = BsH[tig * BSTRP2 + c]; bh[nt][1] = BsH[(tig + 4) * BSTRP2 + c];
            bl[nt][0] = BsL[tig * BSTRP2 + c]; bl[nt][1] = BsL[(tig + 4) * BSTRP2 + c];
        }
#pragma unroll
        for (int mt = 0; mt < 4; mt++)
#pragma unroll
            for (int nt = 0; nt < 8; nt++) mma16(acc[mt][nt], ah[mt], bh[nt]);
#pragma unroll
        for (int mt = 0; mt < 4; mt++)
#pragma unroll
            for (int nt = 0; nt < 8; nt++) mma16(acc[mt][nt], ah[mt], bl[nt]);
#pragma unroll
        for (int mt = 0; mt < 4; mt++)
#pragma unroll
            for (int nt = 0; nt < 8; nt++) mma16(acc[mt][nt], al[mt], bh[nt]);
        __syncthreads();
    }

#pragma unroll
    for (int mt = 0; mt < 4; mt++) {
        int t = mt * 16 + gid;
#pragma unroll
        for (int nt = 0; nt < 8; nt++) {
            int n = col0 + wn * 64 + nt * 8 + tig * 2;
            float b0 = w.x * be[e.x * H_DIM + n]     + w.y * be[e.y * H_DIM + n];
            float b1 = w.x * be[e.x * H_DIM + n + 1] + w.y * be[e.y * H_DIM + n + 1];
            if (t < S)
                *(float2*)(out + ((size_t)i * S + t) * H_DIM + n) =
                    make_float2(acc[mt][nt][0] + b0, acc[mt][nt][1] + b1);
            if (t + 8 < S)
                *(float2*)(out + ((size_t)i * S + t + 8) * H_DIM + n) =
                    make_float2(acc[mt][nt][2] + b0, acc[mt][nt][3] + b1);
        }
    }
}

// ---- MoE S=65 (bf16x3): block 80x128, 4 warps each 80x32, 3 CTAs/SM -------
__global__ __launch_bounds__(128, 3) void moe3_tc(
    const float* __restrict__ cls, const float* __restrict__ tok,
    const float* __restrict__ We, const float* __restrict__ be,
    const int2* __restrict__ eidx, const float2* __restrict__ ew,
    float* __restrict__ out)
{
    const int S = 65;
    __shared__ uint32_t AsH[80 * ASTRP], AsL[80 * ASTRP];
    __shared__ uint32_t BsH[8 * BSTRP], BsL[8 * BSTRP];

    const int i = blockIdx.z;
    const int col0 = blockIdx.x * 128;
    const int2 e = eidx[i];
    const float2 w = ew[i];
    const float* W0 = We + (size_t)e.x * H_DIM * H_DIM;
    const float* W1 = We + (size_t)e.y * H_DIM * H_DIM;

    const int tid = threadIdx.x;
    const int warp = tid >> 5, lane = tid & 31;
    const int wn = warp;
    const int gid = lane >> 2, tig = lane & 3;
    const int bk = tid >> 4;
    const int nc = (tid & 15) * 8;

    const float* rp = nullptr;
    if (tid < S)
        rp = (tid == 0) ? (cls + (size_t)i * H_DIM)
                        : (tok + ((size_t)i * (S - 1) + (tid - 1)) * H_DIM);

    float acc[5][4][4];
#pragma unroll
    for (int a = 0; a < 5; a++)
#pragma unroll
        for (int b = 0; b < 4; b++)
#pragma unroll
            for (int c = 0; c < 4; c++) acc[a][b][c] = 0.f;

    for (int kb = 0; kb < H_DIM / 16; kb++) {
        const int k0 = kb * 16;
        if (tid < 80) {
#pragma unroll
            for (int q = 0; q < 4; q++) {
                float4 v = make_float4(0.f, 0.f, 0.f, 0.f);
                if (rp) v = *(const float4*)(rp + k0 + q * 4);
                uint32_t h0, l0, h1, l1;
                split_bf16x2(v.x, v.y, h0, l0);
                split_bf16x2(v.z, v.w, h1, l1);
                *(uint2*)&AsH[tid * ASTRP + q * 2] = make_uint2(h0, h1);
                *(uint2*)&AsL[tid * ASTRP + q * 2] = make_uint2(l0, l1);
            }
        }
        {
            size_t o0 = (size_t)(k0 + 2 * bk) * H_DIM + col0 + nc;
#pragma unroll
            for (int q = 0; q < 2; q++) {
                float4 a0 = *(const float4*)(W0 + o0 + q * 4);
                float4 b0 = *(const float4*)(W1 + o0 + q * 4);
                float4 a1 = *(const float4*)(W0 + o0 + H_DIM + q * 4);
                float4 b1 = *(const float4*)(W1 + o0 + H_DIM + q * 4);
                float4 r0 = make_float4(w.x * a0.x + w.y * b0.x, w.x * a0.y + w.y * b0.y,
                                        w.x * a0.z + w.y * b0.z, w.x * a0.w + w.y * b0.w);
                float4 r1 = make_float4(w.x * a1.x + w.y * b1.x, w.x * a1.y + w.y * b1.y,
                                        w.x * a1.z + w.y * b1.z, w.x * a1.w + w.y * b1.w);
                uint4 h, l;
                splitB4(r0, r1, h, l);
                *(uint4*)&BsH[bk * BSTRP + nc + q * 4] = h;
                *(uint4*)&BsL[bk * BSTRP + nc + q * 4] = l;
            }
        }
        __syncthreads();

        uint32_t ah[5][4], al[5][4], bh[4][2], bl[4][2];
#pragma unroll
        for (int mt = 0; mt < 5; mt++) {
            int r = (mt * 16 + gid) * ASTRP;
            ah[mt][0] = AsH[r + tig];     ah[mt][1] = AsH[r + 8 * ASTRP + tig];
            ah[mt][2] = AsH[r + tig + 4]; ah[mt][3] = AsH[r + 8 * ASTRP + tig + 4];
            al[mt][0] = AsL[r + tig];     al[mt][1] = AsL[r + 8 * ASTRP + tig];
            al[mt][2] = AsL[r + tig + 4]; al[mt][3] = AsL[r + 8 * ASTRP + tig + 4];
        }
#pragma unroll
        for (int nt = 0; nt < 4; nt++) {
            int c = wn * 32 + nt * 8 + gid;
            bh[nt][0] = BsH[tig * BSTRP + c]; bh[nt][1] = BsH[(tig + 4) * BSTRP + c];
            bl[nt][0] = BsL[tig * BSTRP + c]; bl[nt][1] = BsL[(tig + 4) * BSTRP + c];
        }
#pragma unroll
        for (int mt = 0; mt < 5; mt++)
#pragma unroll
            for (int nt = 0; nt < 4; nt++) mma16(acc[mt][nt], ah[mt], bh[nt]);
#pragma unroll
        for (int mt = 0; mt < 5; mt++)
#pragma unroll
            for (int nt = 0; nt < 4; nt++) mma16(acc[mt][nt], ah[mt], bl[nt]);
#pragma unroll
        for (int mt = 0; mt < 5; mt++)
#pragma unroll
            for (int nt = 0; nt < 4; nt++) mma16(acc[mt][nt], al[mt], bh[nt]);
        __syncthreads();
    }

#pragma unroll
    for (int mt = 0; mt < 5; mt++) {
        int t = mt * 16 + gid;
#pragma unroll
        for (int nt = 0; nt < 4; nt++) {
            int n = col0 + wn * 32 + nt * 8 + tig * 2;
            float b0 = w.x * be[e.x * H_DIM + n]     + w.y * be[e.y * H_DIM + n];
            float b1 = w.x * be[e.x * H_DIM + n + 1] + w.y * be[e.y * H_DIM + n + 1];
            if (t < S)
                *(float2*)(out + ((size_t)i * S + t) * H_DIM + n) =
                    make_float2(acc[mt][nt][0] + b0, acc[mt][nt][1] + b1);
            if (t + 8 < S)
                *(float2*)(out + ((size_t)i * S + t + 8) * H_DIM + n) =
                    make_float2(acc[mt][nt][2] + b0, acc[mt][nt][3] + b1);
        }
    }
}

// ------ router weight folding + projection-weight pre-split (one kernel) ----
__global__ void combine_w_kernel(const float* __restrict__ Wt, const float* __restrict__ Wi,
                                 const float* __restrict__ Wr,
                                 float* __restrict__ WcT, float* __restrict__ WcI,
                                 uint32_t* __restrict__ Wh, uint32_t* __restrict__ Wl)
{
    int idx = blockIdx.x * blockDim.x + threadIdx.x;
    if (idx < D_IN * N_EXP) {
        int k = idx >> 3, e = idx & 7;
        float st = 0.f, si = 0.f;
        for (int h = 0; h < H_DIM; h++) {
            float wr = Wr[h * N_EXP + e];
            st += Wt[(size_t)k * H_DIM + h] * wr;
            si += Wi[(size_t)k * H_DIM + h] * wr;
        }
        WcT[idx] = st;
        WcI[idx] = si;
    }
    if (idx < 2 * WSP_SZ) {
        int which = idx / WSP_SZ;
        int rem = idx - which * WSP_SZ;
        int p = rem / H_DIM, n = rem - (rem / H_DIM) * H_DIM;
        const float* W = which ? Wi : Wt;
        float a = W[(size_t)(2 * p) * H_DIM + n];
        float b = W[(size_t)(2 * p + 1) * H_DIM + n];
        uint32_t h, l;
        split_bf16x2(a, b, h, l);
        Wh[idx] = h;
        Wl[idx] = l;
    }
}

__global__ void bterm_kernel(const float* __restrict__ bt, const float* __restrict__ bi,
                             const float* __restrict__ Wr, const float* __restrict__ br,
                             float* __restrict__ bterm)
{
    int e = threadIdx.x;
    if (e < N_EXP) {
        float sA = 0.f, sB = 0.f;
        for (int h = 0; h < H_DIM; h++) {
            float wr = Wr[h * N_EXP + e];
            sA += (bi[h] + 64.f * bt[h]) * wr;
            sB += (bt[h] + 49.f * bi[h]) * wr;
        }
        bterm[e]         = sA / 65.f + br[e];
        bterm[N_EXP + e] = sB / 50.f + br[e];
    }
}

// -------- router: stage1 bandwidth token-sum (float4), stage2 logits -------
__global__ __launch_bounds__(256) void router2_kernel(
    const float* __restrict__ cls, const float* __restrict__ tok, int Sm1,
    const float* __restrict__ WcCls, const float* __restrict__ WcTok,
    const float* __restrict__ bt,
    int2* __restrict__ eidx, float2* __restrict__ ew)
{
    const int i = blockIdx.x, tid = threadIdx.x;
    __shared__ float sumtok[D_IN];
    __shared__ float red[8][N_EXP];
    __shared__ float logits[N_EXP];

    if (tid < 192) {
        const float4* tp = (const float4*)(tok + (size_t)i * Sm1 * D_IN) + tid;
        float4 s0 = make_float4(0.f, 0.f, 0.f, 0.f), s1 = s0, s2 = s0, s3 = s0;
        int t = 0;
        for (; t + 4 <= Sm1; t += 4) {
            float4 a = tp[(size_t)(t + 0) * 192];
            float4 b = tp[(size_t)(t + 1) * 192];
            float4 c = tp[(size_t)(t + 2) * 192];
            float4 d = tp[(size_t)(t + 3) * 192];
            s0.x += a.x; s0.y += a.y; s0.z += a.z; s0.w += a.w;
            s1.x += b.x; s1.y += b.y; s1.z += b.z; s1.w += b.w;
            s2.x += c.x; s2.y += c.y; s2.z += c.z; s2.w += c.w;
            s3.x += d.x; s3.y += d.y; s3.z += d.z; s3.w += d.w;
        }
        for (; t < Sm1; t++) {
            float4 a = tp[(size_t)t * 192];
            s0.x += a.x; s0.y += a.y; s0.z += a.z; s0.w += a.w;
        }
        float4 s = make_float4(s0.x + s1.x + s2.x + s3.x, s0.y + s1.y + s2.y + s3.y,
                               s0.z + s1.z + s2.z + s3.z, s0.w + s1.w + s2.w + s3.w);
        *(float4*)&sumtok[tid * 4] = s;
    }
    __syncthreads();

    const int warp = tid >> 5, lane = tid & 31;
    {
        float part[N_EXP];
#pragma unroll
        for (int e = 0; e < N_EXP; e++) part[e] = 0.f;
        for (int c = tid; c < D_IN; c += 256) {
            float cl = cls[(size_t)i * D_IN + c];
            float s = sumtok[c];
#pragma unroll
            for (int e = 0; e < N_EXP; e++)
                part[e] += cl * WcCls[c * N_EXP + e] + s * WcTok[c * N_EXP + e];
        }
#pragma unroll
        for (int o = 16; o; o >>= 1)
#pragma unroll
            for (int e = 0; e < N_EXP; e++)
                part[e] += __shfl_down_sync(0xffffffffu, part[e], o);
        if (lane == 0)
#pragma unroll
            for (int e = 0; e < N_EXP; e++) red[warp][e] = part[e];
    }
    __syncthreads();
    if (tid < N_EXP) {
        float l = 0.f;
        for (int wq = 0; wq < 8; wq++) l += red[wq][tid];
        logits[tid] = l / (float)(Sm1 + 1) + bt[tid];
    }
    __syncthreads();
    if (tid == 0) {
        int b0 = 0;
        for (int e = 1; e < N_EXP; e++)
            if (logits[e] > logits[b0]) b0 = e;
        int b1 = (b0 == 0) ? 1 : 0;
        for (int e = 0; e < N_EXP; e++)
            if (e != b0 && logits[e] > logits[b1]) b1 = e;
        float e1v = expf(logits[b1] - logits[b0]);
        float inv = 1.0f / (1.0f + e1v);
        eidx[i] = make_int2(b0, b1);
        ew[i] = make_float2(inv, e1v * inv);
    }
}

// ------------- cross attention: tokens resident in dynamic smem -------------
__global__ __launch_bounds__(256) void cross_kernel(
    const float* __restrict__ moe_out, int S, float* __restrict__ ctx)
{
    extern __shared__ float tokbuf[];
    __shared__ float prob[64];
    const int i = blockIdx.x;
    const int tid = threadIdx.x;
    const float* base = moe_out + (size_t)i * S * H_DIM;

    {
        const float4* src = (const float4*)base;
        float4* dst = (float4*)tokbuf;
        const int n4 = S * (H_DIM / 4);
        for (int idx = tid; idx < n4; idx += 256) dst[idx] = src[idx];
    }
    __syncthreads();

    const int nt = S - 1;
    const int warp = tid >> 5, lane = tid & 31;
    for (int s = warp; s < nt; s += 8) {
        const float4* tr = (const float4*)(tokbuf + (s + 1) * H_DIM);
        const float4* cl = (const float4*)tokbuf;
        float p = 0.f;
#pragma unroll
        for (int q = 0; q < 4; q++) {
            float4 a = cl[lane + 32 * q];
            float4 b = tr[lane + 32 * q];
            p += a.x * b.x + a.y * b.y + a.z * b.z + a.w * b.w;
        }
#pragma unroll
        for (int o = 16; o; o >>= 1) p += __shfl_down_sync(0xffffffffu, p, o);
        if (lane == 0) prob[s] = p;
    }
    __syncthreads();

    if (tid == 0) {
        float mx = -1e30f;
        for (int s = 0; s < nt; s++) mx = fmaxf(mx, prob[s]);
        float sum = 0.f;
        for (int s = 0; s < nt; s++) { float e = expf(prob[s] - mx); prob[s] = e; sum += e; }
        float inv = 1.0f / sum;
        for (int s = 0; s < nt; s++) prob[s] *= inv;
    }
    __syncthreads();

    float2 acc = make_float2(0.f, 0.f);
    const float2* b2 = (const float2*)(tokbuf + H_DIM) + tid;
#pragma unroll 4
    for (int s = 0; s < nt; s++) {
        float2 v = b2[(size_t)s * (H_DIM / 2)];
        float pw = prob[s];
        acc.x += pw * v.x; acc.y += pw * v.y;
    }
    ((float2*)(ctx + (size_t)i * H_DIM))[tid] = acc;
}

// --------------------------- gate + residual + LN ---------------------------
__global__ __launch_bounds__(256) void gate_ln_kernel(
    const float* __restrict__ ori, const float* __restrict__ ctx,
    const float* __restrict__ Wg, const float* __restrict__ bg,
    const float* __restrict__ ls, const float* __restrict__ lb,
    float* __restrict__ out, int gate_from_ctx)
{
    const int i = blockIdx.x;
    __shared__ float v[H_DIM];
    __shared__ float red[256];
    const int tid = threadIdx.x;
    const float* orow = ori + (size_t)i * H_DIM;
    const float* crow = ctx + (size_t)i * H_DIM;

    float p = 0.f;
    for (int c = tid; c < H_DIM; c += 256) {
        float gs = gate_from_ctx ? crow[c] : orow[c];
        p += gs * Wg[c];
    }
    red[tid] = p; __syncthreads();
    for (int o = 128; o; o >>= 1) { if (tid < o) red[tid] += red[tid + o]; __syncthreads(); }
    float gate = tanhf(red[0] + bg[0]);
    __syncthreads();

    float sum = 0.f;
    for (int c = tid; c < H_DIM; c += 256) {
        float val = orow[c] * gate + crow[c];
        v[c] = val; sum += val;
    }
    red[tid] = sum; __syncthreads();
    for (int o = 128; o; o >>= 1) { if (tid < o) red[tid] += red[tid + o]; __syncthreads(); }
    float mean = red[0] / (float)H_DIM;
    __syncthreads();

    float var = 0.f;
    for (int c = tid; c < H_DIM; c += 256) { float d = v[c] - mean; var += d * d; }
    red[tid] = var; __syncthreads();
    for (int o = 128; o; o >>= 1) { if (tid < o) red[tid] += red[tid + o]; __syncthreads(); }
    float rstd = rsqrtf(red[0] / (float)H_DIM + 1e-5f);

    for (int c = tid; c < H_DIM; c += 256)
        out[(size_t)i * H_DIM + c] = (v[c] - mean) * rstd * ls[c] + lb[c];
}

// -------------------------------- final score -------------------------------
__global__ __launch_bounds__(256) void score_kernel(
    const float* __restrict__ mti, const float* __restrict__ eti,
    const float* __restrict__ mit, const float* __restrict__ eit,
    float* __restrict__ out)
{
    __shared__ float As[8][64];
    __shared__ float Bs[8][64];
    const int n0 = blockIdx.x * 64;
    const int b0 = blockIdx.y * 64;
    const int tid = threadIdx.x;
    const int tx = tid & 15, ty = tid >> 4;
    const int lrow = tid >> 2, lcol = (tid & 3) * 2;

    float acc[4][4];
#pragma unroll
    for (int q = 0; q < 4; q++)
#pragma unroll
        for (int r = 0; r < 4; r++) acc[q][r] = 0.f;

#pragma unroll
    for (int pass = 0; pass < 2; pass++) {
        const float* A = pass ? mit : mti;
        const float* B = pass ? eit : eti;
        for (int k0 = 0; k0 < H_DIM; k0 += 8) {
            float2 av = *(const float2*)(A + (size_t)(b0 + lrow) * H_DIM + k0 + lcol);
            As[lcol][lrow] = av.x; As[lcol + 1][lrow] = av.y;
            float2 bv = *(const float2*)(B + (size_t)(n0 + lrow) * H_DIM + k0 + lcol);
            Bs[lcol][lrow] = bv.x; Bs[lcol + 1][lrow] = bv.y;
            __syncthreads();
#pragma unroll
            for (int k = 0; k < 8; k++) {
                float a[4], b[4];
#pragma unroll
                for (int q = 0; q < 4; q++) a[q] = As[k][ty * 4 + q];
#pragma unroll
                for (int q = 0; q < 4; q++) b[q] = Bs[k][tx * 4 + q];
#pragma unroll
                for (int q = 0; q < 4; q++)
#pragma unroll
                    for (int r = 0; r < 4; r++) acc[q][r] += a[q] * b[r];
            }
            __syncthreads();
        }
    }
#pragma unroll
    for (int q = 0; q < 4; q++)
#pragma unroll
        for (int r = 0; r < 4; r++)
            out[(size_t)(b0 + ty * 4 + q) * N_ENT + (n0 + tx * 4 + r)] = 0.5f * acc[q][r];
}

// ---------------------------------- launch ----------------------------------
extern "C" void kernel_launch(void* const* d_in, const int* in_sizes, int n_in,
                              void* d_out, int out_size)
{
    const float* etc_in = (const float*)d_in[0];
    const float* ett_in = (const float*)d_in[1];
    const float* mtc_in = (const float*)d_in[2];
    const float* mtt_in = (const float*)d_in[3];
    const float* eic_in = (const float*)d_in[4];
    const float* eit_in = (const float*)d_in[5];
    const float* mic_in = (const float*)d_in[6];
    const float* mit_in = (const float*)d_in[7];
    const float* W_text = (const float*)d_in[8];
    const float* b_text = (const float*)d_in[9];
    const float* W_img  = (const float*)d_in[10];
    const float* b_img  = (const float*)d_in[11];
    const float* W_gate = (const float*)d_in[12];
    const float* b_gate = (const float*)d_in[13];
    const float* ln_s   = (const float*)d_in[14];
    const float* ln_b   = (const float*)d_in[15];
    const float* W_rout = (const float*)d_in[16];
    const float* b_rout = (const float*)d_in[17];
    const float* W_exp  = (const float*)d_in[18];
    const float* b_exp  = (const float*)d_in[19];
    float* out = (float*)d_out;

    float *p_etc, *p_eic, *p_mtc, *p_mic, *p_ett, *p_eit, *p_mtt, *p_mit;
    float *p_etim, *p_mtim, *p_eitm, *p_mitm;
    float *p_ctx0, *p_ctx1, *p_ctx2, *p_ctx3;
    float *p_feti, *p_fmti, *p_feit, *p_fmit;
    float *p_wct, *p_wci, *p_bt;
    uint32_t *p_wh, *p_wl;
    int2* p_eidx; float2* p_ew;
    cudaGetSymbolAddress((void**)&p_etc, g_etc);
    cudaGetSymbolAddress((void**)&p_eic, g_eic);
    cudaGetSymbolAddress((void**)&p_mtc, g_mtc);
    cudaGetSymbolAddress((void**)&p_mic, g_mic);
    cudaGetSymbolAddress((void**)&p_ett, g_ett);
    cudaGetSymbolAddress((void**)&p_eit, g_eit);
    cudaGetSymbolAddress((void**)&p_mtt, g_mtt);
    cudaGetSymbolAddress((void**)&p_mit, g_mit);
    cudaGetSymbolAddress((void**)&p_etim, g_eti_m);
    cudaGetSymbolAddress((void**)&p_mtim, g_mti_m);
    cudaGetSymbolAddress((void**)&p_eitm, g_eit_m);
    cudaGetSymbolAddress((void**)&p_mitm, g_mit_m);
    cudaGetSymbolAddress((void**)&p_ctx0, g_ctx0);
    cudaGetSymbolAddress((void**)&p_ctx1, g_ctx1);
    cudaGetSymbolAddress((void**)&p_ctx2, g_ctx2);
    cudaGetSymbolAddress((void**)&p_ctx3, g_ctx3);
    cudaGetSymbolAddress((void**)&p_feti, g_fe_ti);
    cudaGetSymbolAddress((void**)&p_fmti, g_fm_ti);
    cudaGetSymbolAddress((void**)&p_feit, g_fe_it);
    cudaGetSymbolAddress((void**)&p_fmit, g_fm_it);
    cudaGetSymbolAddress((void**)&p_wct, g_wc_text);
    cudaGetSymbolAddress((void**)&p_wci, g_wc_img);
    cudaGetSymbolAddress((void**)&p_bt, g_bterm);
    cudaGetSymbolAddress((void**)&p_wh, g_wsp_h);
    cudaGetSymbolAddress((void**)&p_wl, g_wsp_l);
    cudaGetSymbolAddress((void**)&p_eidx, g_eidx);
    cudaGetSymbolAddress((void**)&p_ew,   g_ew);

    const int CROSS_SMEM = 65 * H_DIM * 4;
    cudaFuncSetAttribute(cross_kernel, cudaFuncAttributeMaxDynamicSharedMemorySize, CROSS_SMEM);

    dim3 blk(256);
    dim3 blkg(128);

    // 1: prep (router fold + proj weight pre-split)
    combine_w_kernel<<<(2 * WSP_SZ + 255) / 256, blk>>>(W_text, W_img, W_rout,
                                                        p_wct, p_wci, p_wh, p_wl);
    // 2: bias terms
    bterm_kernel<<<1, 32>>>(b_text, b_img, W_rout, b_rout, p_bt);

    // 3: first big router
    router2_kernel<<<N_ENT, blk>>>(eic_in, ett_in, T_TOK, p_wci, p_wct, p_bt,
                                   p_eidx + 0 * N_ENT, p_ew + 0 * N_ENT);

    // 4: big ett projection — positioned for ncu capture
    proj_tc<<<dim3(4, N_ENT * T_TOK / 128), blkg>>>(ett_in, p_wh, p_wl, b_text, p_ett, N_ENT * T_TOK);

    // remaining routers
    router2_kernel<<<BATCH, blk>>>(mic_in, mtt_in, T_TOK, p_wci, p_wct, p_bt,
                                   p_eidx + 1 * N_ENT, p_ew + 1 * N_ENT);
    router2_kernel<<<N_ENT, blk>>>(etc_in, eit_in, P_TOK, p_wct, p_wci, p_bt + N_EXP,
                                   p_eidx + 2 * N_ENT, p_ew + 2 * N_ENT);
    router2_kernel<<<BATCH, blk>>>(mtc_in, mit_in, P_TOK, p_wct, p_wci, p_bt + N_EXP,
                                   p_eidx + 3 * N_ENT, p_ew + 3 * N_ENT);

    // remaining projections (text -> offset 0, img -> offset WSP_SZ)
    proj_tc<<<dim3(4, N_ENT / 128), blkg>>>(etc_in, p_wh, p_wl, b_text, p_etc, N_ENT);
    proj_tc<<<dim3(4, BATCH / 128), blkg>>>(mtc_in, p_wh, p_wl, b_text, p_mtc, BATCH);
    proj_tc<<<dim3(4, BATCH * T_TOK / 128), blkg>>>(mtt_in, p_wh, p_wl, b_text, p_mtt, BATCH * T_TOK);
    proj_tc<<<dim3(4, N_ENT / 128), blkg>>>(eic_in, p_wh + WSP_SZ, p_wl + WSP_SZ, b_img, p_eic, N_ENT);
    proj_tc<<<dim3(4, N_ENT * P_TOK / 128), blkg>>>(eit_in, p_wh + WSP_SZ, p_wl + WSP_SZ, b_img, p_eit, N_ENT * P_TOK);
    proj_tc<<<dim3(4, BATCH / 128), blkg>>>(mic_in, p_wh + WSP_SZ, p_wl + WSP_SZ, b_img, p_mic, BATCH);
    proj_tc<<<dim3(4, BATCH * P_TOK / 128), blkg>>>(mit_in, p_wh + WSP_SZ, p_wl + WSP_SZ, b_img, p_mit, BATCH * P_TOK);

    // MoE GEMMs (combined expert pair, bf16x3)
    moe2_tc<<<dim3(2, 1, N_ENT), blkg>>>(p_etc, p_eit, W_exp, b_exp,
                                         p_eidx + 0 * N_ENT, p_ew + 0 * N_ENT, p_etim);
    moe2_tc<<<dim3(2, 1, BATCH), blkg>>>(p_mtc, p_mit, W_exp, b_exp,
                                         p_eidx + 1 * N_ENT, p_ew + 1 * N_ENT, p_mtim);
    moe3_tc<<<dim3(4, 1, N_ENT), blkg>>>(p_eic, p_ett, W_exp, b_exp,
                                         p_eidx + 2 * N_ENT, p_ew + 2 * N_ENT, p_eitm);
    moe3_tc<<<dim3(4, 1, BATCH), blkg>>>(p_mic, p_mtt, W_exp, b_exp,
                                         p_eidx + 3 * N_ENT, p_ew + 3 * N_ENT, p_mitm);

    // cross attention (tokens smem-resident)
    cross_kernel<<<N_ENT, blk, 50 * H_DIM * 4>>>(p_etim, 50, p_ctx0);
    cross_kernel<<<BATCH, blk, 50 * H_DIM * 4>>>(p_mtim, 50, p_ctx1);
    cross_kernel<<<N_ENT, blk, 65 * H_DIM * 4>>>(p_eitm, 65, p_ctx2);
    cross_kernel<<<BATCH, blk, 65 * H_DIM * 4>>>(p_mitm, 65, p_ctx3);

    // gate + residual + LN
    gate_ln_kernel<<<N_ENT, blk>>>(p_etc, p_ctx0, W_gate, b_gate, ln_s, ln_b, p_feti, 1);
    gate_ln_kernel<<<BATCH, blk>>>(p_mtc, p_ctx1, W_gate, b_gate, ln_s, ln_b, p_fmti, 0);
    gate_ln_kernel<<<N_ENT, blk>>>(p_eic, p_ctx2, W_gate, b_gate, ln_s, ln_b, p_feit, 1);
    gate_ln_kernel<<<BATCH, blk>>>(p_mic, p_ctx3, W_gate, b_gate, ln_s, ln_b, p_fmit, 0);

    // final score
    score_kernel<<<dim3(N_ENT / 64, BATCH / 64), blk>>>(p_fmti, p_feti, p_fmit, p_feit, out);
}

// round 15
// speedup vs baseline: 1.1180x; 1.1180x over previous
#include <cuda_runtime.h>
#include <cuda_bf16.h>
#include <math.h>
#include <stdint.h>

#define N_ENT 1024
#define BATCH 128
#define T_TOK 64
#define P_TOK 49
#define D_IN 768
#define H_DIM 512
#define N_EXP 8
#define NKP (D_IN / 2)
#define WSP_SZ (NKP * H_DIM)

// ----------------------------- static scratch ------------------------------
__device__ float g_etc[N_ENT * H_DIM];
__device__ float g_eic[N_ENT * H_DIM];
__device__ float g_mtc[BATCH * H_DIM];
__device__ float g_mic[BATCH * H_DIM];
__device__ float g_ett[N_ENT * T_TOK * H_DIM];
__device__ float g_eit[N_ENT * P_TOK * H_DIM];
__device__ float g_mtt[BATCH * T_TOK * H_DIM];
__device__ float g_mit[BATCH * P_TOK * H_DIM];

__device__ float g_eti_m[N_ENT * 50 * H_DIM];
__device__ float g_mti_m[BATCH * 50 * H_DIM];
__device__ float g_eit_m[N_ENT * 65 * H_DIM];
__device__ float g_mit_m[BATCH * 65 * H_DIM];

__device__ int2   g_eidx[4][N_ENT];
__device__ float2 g_ew[4][N_ENT];

__device__ float g_ctx0[N_ENT * H_DIM];
__device__ float g_ctx1[BATCH * H_DIM];
__device__ float g_ctx2[N_ENT * H_DIM];
__device__ float g_ctx3[BATCH * H_DIM];

__device__ float g_fe_ti[N_ENT * H_DIM];
__device__ float g_fm_ti[BATCH * H_DIM];
__device__ float g_fe_it[N_ENT * H_DIM];
__device__ float g_fm_it[BATCH * H_DIM];

__device__ float g_wc_text[D_IN * N_EXP];
__device__ float g_wc_img[D_IN * N_EXP];
__device__ float g_bterm[2 * N_EXP];

// pre-split projection weights: packed bf16 pairs (k, k+1), [pair][n]
__device__ uint32_t g_wsp_h[2 * WSP_SZ];
__device__ uint32_t g_wsp_l[2 * WSP_SZ];

// --------------------------- bf16 split helpers -----------------------------
__device__ __forceinline__ void split_bf16x2(float a, float b, uint32_t& h, uint32_t& l)
{
    __nv_bfloat162 hp = __floats2bfloat162_rn(a, b);
    float ra = a - __bfloat162float(hp.x);
    float rb = b - __bfloat162float(hp.y);
    __nv_bfloat162 lp = __floats2bfloat162_rn(ra, rb);
    h = *(uint32_t*)&hp;
    l = *(uint32_t*)&lp;
}

__device__ __forceinline__ void splitB4(float4 r0, float4 r1, uint4& h, uint4& l)
{
    split_bf16x2(r0.x, r1.x, h.x, l.x);
    split_bf16x2(r0.y, r1.y, h.y, l.y);
    split_bf16x2(r0.z, r1.z, h.z, l.z);
    split_bf16x2(r0.w, r1.w, h.w, l.w);
}

__device__ __forceinline__ void mma16(float* c, const uint32_t* a, const uint32_t* b)
{
    asm volatile(
        "mma.sync.aligned.m16n8k16.row.col.f32.bf16.bf16.f32 "
        "{%0,%1,%2,%3}, {%4,%5,%6,%7}, {%8,%9}, {%0,%1,%2,%3};"
        : "+f"(c[0]), "+f"(c[1]), "+f"(c[2]), "+f"(c[3])
        : "r"(a[0]), "r"(a[1]), "r"(a[2]), "r"(a[3]), "r"(b[0]), "r"(b[1]));
}

#define ASTRP 12
#define BSTRP 136
#define BSTRP2 264

// ------------------ proj core (bf16x3), shared by both entry points --------
__device__ __forceinline__ void proj_body(
    const float* __restrict__ A,
    const uint32_t* __restrict__ Wh, const uint32_t* __restrict__ Wl,
    const float* __restrict__ bias, float* __restrict__ C,
    int row0, int col0)
{
    __shared__ uint32_t AsH[128 * ASTRP], AsL[128 * ASTRP];
    __shared__ uint32_t BsH[8 * BSTRP], BsL[8 * BSTRP];

    const int tid = threadIdx.x;
    const int warp = tid >> 5, lane = tid & 31;
    const int wm = warp >> 1, wn = warp & 1;
    const int gid = lane >> 2, tig = lane & 3;
    const int bk = tid >> 4;
    const int nc = (tid & 15) * 8;

    float acc[4][8][4];
#pragma unroll
    for (int a = 0; a < 4; a++)
#pragma unroll
        for (int b = 0; b < 8; b++)
#pragma unroll
            for (int c = 0; c < 4; c++) acc[a][b][c] = 0.f;

    const float* Arow = A + (size_t)(row0 + tid) * D_IN;

    for (int kb = 0; kb < D_IN / 16; kb++) {
        const int k0 = kb * 16;
#pragma unroll
        for (int q = 0; q < 4; q++) {
            float4 v = *(const float4*)(Arow + k0 + q * 4);
            uint32_t h0, l0, h1, l1;
            split_bf16x2(v.x, v.y, h0, l0);
            split_bf16x2(v.z, v.w, h1, l1);
            *(uint2*)&AsH[tid * ASTRP + q * 2] = make_uint2(h0, h1);
            *(uint2*)&AsL[tid * ASTRP + q * 2] = make_uint2(l0, l1);
        }
        {
            size_t off = (size_t)(kb * 8 + bk) * H_DIM + col0 + nc;
            *(uint4*)&BsH[bk * BSTRP + nc]     = *(const uint4*)(Wh + off);
            *(uint4*)&BsH[bk * BSTRP + nc + 4] = *(const uint4*)(Wh + off + 4);
            *(uint4*)&BsL[bk * BSTRP + nc]     = *(const uint4*)(Wl + off);
            *(uint4*)&BsL[bk * BSTRP + nc + 4] = *(const uint4*)(Wl + off + 4);
        }
        __syncthreads();

        uint32_t ah[4][4], al[4][4], bh[8][2], bl[8][2];
#pragma unroll
        for (int mt = 0; mt < 4; mt++) {
            int r = (wm * 64 + mt * 16 + gid) * ASTRP;
            ah[mt][0] = AsH[r + tig];     ah[mt][1] = AsH[r + 8 * ASTRP + tig];
            ah[mt][2] = AsH[r + tig + 4]; ah[mt][3] = AsH[r + 8 * ASTRP + tig + 4];
            al[mt][0] = AsL[r + tig];     al[mt][1] = AsL[r + 8 * ASTRP + tig];
            al[mt][2] = AsL[r + tig + 4]; al[mt][3] = AsL[r + 8 * ASTRP + tig + 4];
        }
#pragma unroll
        for (int nt = 0; nt < 8; nt++) {
            int c = wn * 64 + nt * 8 + gid;
            bh[nt][0] = BsH[tig * BSTRP + c]; bh[nt][1] = BsH[(tig + 4) * BSTRP + c];
            bl[nt][0] = BsL[tig * BSTRP + c]; bl[nt][1] = BsL[(tig + 4) * BSTRP + c];
        }
#pragma unroll
        for (int mt = 0; mt < 4; mt++)
#pragma unroll
            for (int nt = 0; nt < 8; nt++) mma16(acc[mt][nt], ah[mt], bh[nt]);
#pragma unroll
        for (int mt = 0; mt < 4; mt++)
#pragma unroll
            for (int nt = 0; nt < 8; nt++) mma16(acc[mt][nt], ah[mt], bl[nt]);
#pragma unroll
        for (int mt = 0; mt < 4; mt++)
#pragma unroll
            for (int nt = 0; nt < 8; nt++) mma16(acc[mt][nt], al[mt], bh[nt]);
        __syncthreads();
    }

#pragma unroll
    for (int mt = 0; mt < 4; mt++) {
        int m = row0 + wm * 64 + mt * 16 + gid;
#pragma unroll
        for (int nt = 0; nt < 8; nt++) {
            int n = col0 + wn * 64 + nt * 8 + tig * 2;
            float2 bv = *(const float2*)(bias + n);
            *(float2*)(C + (size_t)m * H_DIM + n) =
                make_float2(acc[mt][nt][0] + bv.x, acc[mt][nt][1] + bv.y);
            *(float2*)(C + (size_t)(m + 8) * H_DIM + n) =
                make_float2(acc[mt][nt][2] + bv.x, acc[mt][nt][3] + bv.y);
        }
    }
}

// standard entry: grid (4 col-tiles, M/128 row-tiles)
__global__ __launch_bounds__(128, 2) void proj_tc(
    const float* __restrict__ A,
    const uint32_t* __restrict__ Wh, const uint32_t* __restrict__ Wl,
    const float* __restrict__ bias, float* __restrict__ C, int M)
{
    proj_body(A, Wh, Wl, bias, C, blockIdx.y * 128, blockIdx.x * 128);
}

// fused cls entry: z=0 -> (A0, text weights, C0); z=1 -> (A1, img weights, C1)
__global__ __launch_bounds__(128, 2) void proj_cls_tc(
    const float* __restrict__ A0, const float* __restrict__ A1,
    const uint32_t* __restrict__ Wh, const uint32_t* __restrict__ Wl,
    const float* __restrict__ bt, const float* __restrict__ bi,
    float* __restrict__ C0, float* __restrict__ C1)
{
    const int z = blockIdx.z;
    proj_body(z ? A1 : A0,
              Wh + (size_t)z * WSP_SZ, Wl + (size_t)z * WSP_SZ,
              z ? bi : bt,
              z ? C1 : C0,
              blockIdx.y * 128, blockIdx.x * 128);
}

// -------- MoE S=50 (bf16x3): block 64x256, 4 warps of 64x64 ----------------
__global__ __launch_bounds__(128, 2) void moe2_tc(
    const float* __restrict__ cls, const float* __restrict__ tok,
    const float* __restrict__ We, const float* __restrict__ be,
    const int2* __restrict__ eidx, const float2* __restrict__ ew,
    float* __restrict__ out)
{
    const int S = 50;
    __shared__ uint32_t AsH[64 * ASTRP], AsL[64 * ASTRP];
    __shared__ uint32_t BsH[8 * BSTRP2], BsL[8 * BSTRP2];

    const int i = blockIdx.z;
    const int col0 = blockIdx.x * 256;
    const int2 e = eidx[i];
    const float2 w = ew[i];
    const float* W0 = We + (size_t)e.x * H_DIM * H_DIM;
    const float* W1 = We + (size_t)e.y * H_DIM * H_DIM;

    const int tid = threadIdx.x;
    const int warp = tid >> 5, lane = tid & 31;
    const int wn = warp;
    const int gid = lane >> 2, tig = lane & 3;
    const int bk = tid >> 4;
    const int nc = (tid & 15) * 16;
    const int arow = tid & 63, ahalf = tid >> 6;

    const float* rp = nullptr;
    if (arow < S)
        rp = (arow == 0) ? (cls + (size_t)i * H_DIM)
                         : (tok + ((size_t)i * (S - 1) + (arow - 1)) * H_DIM);

    float acc[4][8][4];
#pragma unroll
    for (int a = 0; a < 4; a++)
#pragma unroll
        for (int b = 0; b < 8; b++)
#pragma unroll
            for (int c = 0; c < 4; c++) acc[a][b][c] = 0.f;

    for (int kb = 0; kb < H_DIM / 16; kb++) {
        const int k0 = kb * 16;
#pragma unroll
        for (int q = 0; q < 2; q++) {
            float4 v = make_float4(0.f, 0.f, 0.f, 0.f);
            if (rp) v = *(const float4*)(rp + k0 + ahalf * 8 + q * 4);
            uint32_t h0, l0, h1, l1;
            split_bf16x2(v.x, v.y, h0, l0);
            split_bf16x2(v.z, v.w, h1, l1);
            *(uint2*)&AsH[arow * ASTRP + ahalf * 4 + q * 2] = make_uint2(h0, h1);
            *(uint2*)&AsL[arow * ASTRP + ahalf * 4 + q * 2] = make_uint2(l0, l1);
        }
        {
            size_t o0 = (size_t)(k0 + 2 * bk) * H_DIM + col0 + nc;
#pragma unroll
            for (int q = 0; q < 4; q++) {
                float4 a0 = *(const float4*)(W0 + o0 + q * 4);
                float4 b0 = *(const float4*)(W1 + o0 + q * 4);
                float4 a1 = *(const float4*)(W0 + o0 + H_DIM + q * 4);
                float4 b1 = *(const float4*)(W1 + o0 + H_DIM + q * 4);
                float4 r0 = make_float4(w.x * a0.x + w.y * b0.x, w.x * a0.y + w.y * b0.y,
                                        w.x * a0.z + w.y * b0.z, w.x * a0.w + w.y * b0.w);
                float4 r1 = make_float4(w.x * a1.x + w.y * b1.x, w.x * a1.y + w.y * b1.y,
                                        w.x * a1.z + w.y * b1.z, w.x * a1.w + w.y * b1.w);
                uint4 h, l;
                splitB4(r0, r1, h, l);
                *(uint4*)&BsH[bk * BSTRP2 + nc + q * 4] = h;
                *(uint4*)&BsL[bk * BSTRP2 + nc + q * 4] = l;
            }
        }
        __syncthreads();

        uint32_t ah[4][4], al[4][4], bh[8][2], bl[8][2];
#pragma unroll
        for (int mt = 0; mt < 4; mt++) {
            int r = (mt * 16 + gid) * ASTRP;
            ah[mt][0] = AsH[r + tig];     ah[mt][1] = AsH[r + 8 * ASTRP + tig];
            ah[mt][2] = AsH[r + tig + 4]; ah[mt][3] = AsH[r + 8 * ASTRP + tig + 4];
            al[mt][0] = AsL[r + tig];     al[mt][1] = AsL[r + 8 * ASTRP + tig];
            al[mt][2] = AsL[r + tig + 4]; al[mt][3] = AsL[r + 8 * ASTRP + tig + 4];
        }
#pragma unroll
        for (int nt = 0; nt < 8; nt++) {
            int c = wn * 64 + nt * 8 + gid;
            bh[nt][0] = BsH[tig * BSTRP2 + c]; bh[nt][1] = BsH[(tig + 4) * BSTRP2 + c];
            bl[nt][0] = BsL[tig * BSTRP2 + c]; bl[nt][1] = BsL[(tig + 4) * BSTRP2 + c];
        }
#pragma unroll
        for (int mt = 0; mt < 4; mt++)
#pragma unroll
            for (int nt = 0; nt < 8; nt++) mma16(acc[mt][nt], ah[mt], bh[nt]);
#pragma unroll
        for (int mt = 0; mt < 4; mt++)
#pragma unroll
            for (int nt = 0; nt < 8; nt++) mma16(acc[mt][nt], ah[mt], bl[nt]);
#pragma unroll
        for (int mt = 0; mt < 4; mt++)
#pragma unroll
            for (int nt = 0; nt < 8; nt++) mma16(acc[mt][nt], al[mt], bh[nt]);
        __syncthreads();
    }

#pragma unroll
    for (int mt = 0; mt < 4; mt++) {
        int t = mt * 16 + gid;
#pragma unroll
        for (int nt = 0; nt < 8; nt++) {
            int n = col0 + wn * 64 + nt * 8 + tig * 2;
            float b0 = w.x * be[e.x * H_DIM + n]     + w.y * be[e.y * H_DIM + n];
            float b1 = w.x * be[e.x * H_DIM + n + 1] + w.y * be[e.y * H_DIM + n + 1];
            if (t < S)
                *(float2*)(out + ((size_t)i * S + t) * H_DIM + n) =
                    make_float2(acc[mt][nt][0] + b0, acc[mt][nt][1] + b1);
            if (t + 8 < S)
                *(float2*)(out + ((size_t)i * S + t + 8) * H_DIM + n) =
                    make_float2(acc[mt][nt][2] + b0, acc[mt][nt][3] + b1);
        }
    }
}

// ---- MoE S=65 (bf16x3): block 80x128, 4 warps each 80x32 ------------------
__global__ __launch_bounds__(128, 2) void moe3_tc(
    const float* __restrict__ cls, const float* __restrict__ tok,
    const float* __restrict__ We, const float* __restrict__ be,
    const int2* __restrict__ eidx, const float2* __restrict__ ew,
    float* __restrict__ out)
{
    const int S = 65;
    __shared__ uint32_t AsH[80 * ASTRP], AsL[80 * ASTRP];
    __shared__ uint32_t BsH[8 * BSTRP], BsL[8 * BSTRP];

    const int i = blockIdx.z;
    const int col0 = blockIdx.x * 128;
    const int2 e = eidx[i];
    const float2 w = ew[i];
    const float* W0 = We + (size_t)e.x * H_DIM * H_DIM;
    const float* W1 = We + (size_t)e.y * H_DIM * H_DIM;

    const int tid = threadIdx.x;
    const int warp = tid >> 5, lane = tid & 31;
    const int wn = warp;
    const int gid = lane >> 2, tig = lane & 3;
    const int bk = tid >> 4;
    const int nc = (tid & 15) * 8;

    const float* rp = nullptr;
    if (tid < S)
        rp = (tid == 0) ? (cls + (size_t)i * H_DIM)
                        : (tok + ((size_t)i * (S - 1) + (tid - 1)) * H_DIM);

    float acc[5][4][4];
#pragma unroll
    for (int a = 0; a < 5; a++)
#pragma unroll
        for (int b = 0; b < 4; b++)
#pragma unroll
            for (int c = 0; c < 4; c++) acc[a][b][c] = 0.f;

    for (int kb = 0; kb < H_DIM / 16; kb++) {
        const int k0 = kb * 16;
        if (tid < 80) {
#pragma unroll
            for (int q = 0; q < 4; q++) {
                float4 v = make_float4(0.f, 0.f, 0.f, 0.f);
                if (rp) v = *(const float4*)(rp + k0 + q * 4);
                uint32_t h0, l0, h1, l1;
                split_bf16x2(v.x, v.y, h0, l0);
                split_bf16x2(v.z, v.w, h1, l1);
                *(uint2*)&AsH[tid * ASTRP + q * 2] = make_uint2(h0, h1);
                *(uint2*)&AsL[tid * ASTRP + q * 2] = make_uint2(l0, l1);
            }
        }
        {
            size_t o0 = (size_t)(k0 + 2 * bk) * H_DIM + col0 + nc;
#pragma unroll
            for (int q = 0; q < 2; q++) {
                float4 a0 = *(const float4*)(W0 + o0 + q * 4);
                float4 b0 = *(const float4*)(W1 + o0 + q * 4);
                float4 a1 = *(const float4*)(W0 + o0 + H_DIM + q * 4);
                float4 b1 = *(const float4*)(W1 + o0 + H_DIM + q * 4);
                float4 r0 = make_float4(w.x * a0.x + w.y * b0.x, w.x * a0.y + w.y * b0.y,
                                        w.x * a0.z + w.y * b0.z, w.x * a0.w + w.y * b0.w);
                float4 r1 = make_float4(w.x * a1.x + w.y * b1.x, w.x * a1.y + w.y * b1.y,
                                        w.x * a1.z + w.y * b1.z, w.x * a1.w + w.y * b1.w);
                uint4 h, l;
                splitB4(r0, r1, h, l);
                *(uint4*)&BsH[bk * BSTRP + nc + q * 4] = h;
                *(uint4*)&BsL[bk * BSTRP + nc + q * 4] = l;
            }
        }
        __syncthreads();

        uint32_t ah[5][4], al[5][4], bh[4][2], bl[4][2];
#pragma unroll
        for (int mt = 0; mt < 5; mt++) {
            int r = (mt * 16 + gid) * ASTRP;
            ah[mt][0] = AsH[r + tig];     ah[mt][1] = AsH[r + 8 * ASTRP + tig];
            ah[mt][2] = AsH[r + tig + 4]; ah[mt][3] = AsH[r + 8 * ASTRP + tig + 4];
            al[mt][0] = AsL[r + tig];     al[mt][1] = AsL[r + 8 * ASTRP + tig];
            al[mt][2] = AsL[r + tig + 4]; al[mt][3] = AsL[r + 8 * ASTRP + tig + 4];
        }
#pragma unroll
        for (int nt = 0; nt < 4; nt++) {
            int c = wn * 32 + nt * 8 + gid;
            bh[nt][0] = BsH[tig * BSTRP + c]; bh[nt][1] = BsH[(tig + 4) * BSTRP + c];
            bl[nt][0] = BsL[tig * BSTRP + c]; bl[nt][1] = BsL[(tig + 4) * BSTRP + c];
        }
#pragma unroll
        for (int mt = 0; mt < 5; mt++)
#pragma unroll
            for (int nt = 0; nt < 4; nt++) mma16(acc[mt][nt], ah[mt], bh[nt]);
#pragma unroll
        for (int mt = 0; mt < 5; mt++)
#pragma unroll
            for (int nt = 0; nt < 4; nt++) mma16(acc[mt][nt], ah[mt], bl[nt]);
#pragma unroll
        for (int mt = 0; mt < 5; mt++)
#pragma unroll
            for (int nt = 0; nt < 4; nt++) mma16(acc[mt][nt], al[mt], bh[nt]);
        __syncthreads();
    }

#pragma unroll
    for (int mt = 0; mt < 5; mt++) {
        int t = mt * 16 + gid;
#pragma unroll
        for (int nt = 0; nt < 4; nt++) {
            int n = col0 + wn * 32 + nt * 8 + tig * 2;
            float b0 = w.x * be[e.x * H_DIM + n]     + w.y * be[e.y * H_DIM + n];
            float b1 = w.x * be[e.x * H_DIM + n + 1] + w.y * be[e.y * H_DIM + n + 1];
            if (t < S)
                *(float2*)(out + ((size_t)i * S + t) * H_DIM + n) =
                    make_float2(acc[mt][nt][0] + b0, acc[mt][nt][1] + b1);
            if (t + 8 < S)
                *(float2*)(out + ((size_t)i * S + t + 8) * H_DIM + n) =
                    make_float2(acc[mt][nt][2] + b0, acc[mt][nt][3] + b1);
        }
    }
}

// ------ router weight folding + projection-weight pre-split (one kernel) ----
__global__ void combine_w_kernel(const float* __restrict__ Wt, const float* __restrict__ Wi,
                                 const float* __restrict__ Wr,
                                 float* __restrict__ WcT, float* __restrict__ WcI,
                                 uint32_t* __restrict__ Wh, uint32_t* __restrict__ Wl)
{
    int idx = blockIdx.x * blockDim.x + threadIdx.x;
    if (idx < D_IN * N_EXP) {
        int k = idx >> 3, e = idx & 7;
        float st = 0.f, si = 0.f;
        for (int h = 0; h < H_DIM; h++) {
            float wr = Wr[h * N_EXP + e];
            st += Wt[(size_t)k * H_DIM + h] * wr;
            si += Wi[(size_t)k * H_DIM + h] * wr;
        }
        WcT[idx] = st;
        WcI[idx] = si;
    }
    if (idx < 2 * WSP_SZ) {
        int which = idx / WSP_SZ;
        int rem = idx - which * WSP_SZ;
        int p = rem / H_DIM, n = rem - (rem / H_DIM) * H_DIM;
        const float* W = which ? Wi : Wt;
        float a = W[(size_t)(2 * p) * H_DIM + n];
        float b = W[(size_t)(2 * p + 1) * H_DIM + n];
        uint32_t h, l;
        split_bf16x2(a, b, h, l);
        Wh[idx] = h;
        Wl[idx] = l;
    }
}

__global__ void bterm_kernel(const float* __restrict__ bt, const float* __restrict__ bi,
                             const float* __restrict__ Wr, const float* __restrict__ br,
                             float* __restrict__ bterm)
{
    int e = threadIdx.x;
    if (e < N_EXP) {
        float sA = 0.f, sB = 0.f;
        for (int h = 0; h < H_DIM; h++) {
            float wr = Wr[h * N_EXP + e];
            sA += (bi[h] + 64.f * bt[h]) * wr;
            sB += (bt[h] + 49.f * bi[h]) * wr;
        }
        bterm[e]         = sA / 65.f + br[e];
        bterm[N_EXP + e] = sB / 50.f + br[e];
    }
}

// -------- router: stage1 bandwidth token-sum (float4), stage2 logits -------
__global__ __launch_bounds__(256) void router2_kernel(
    const float* __restrict__ cls, const float* __restrict__ tok, int Sm1,
    const float* __restrict__ WcCls, const float* __restrict__ WcTok,
    const float* __restrict__ bt,
    int2* __restrict__ eidx, float2* __restrict__ ew)
{
    const int i = blockIdx.x, tid = threadIdx.x;
    __shared__ float sumtok[D_IN];
    __shared__ float red[8][N_EXP];
    __shared__ float logits[N_EXP];

    if (tid < 192) {
        const float4* tp = (const float4*)(tok + (size_t)i * Sm1 * D_IN) + tid;
        float4 s0 = make_float4(0.f, 0.f, 0.f, 0.f), s1 = s0, s2 = s0, s3 = s0;
        int t = 0;
        for (; t + 4 <= Sm1; t += 4) {
            float4 a = tp[(size_t)(t + 0) * 192];
            float4 b = tp[(size_t)(t + 1) * 192];
            float4 c = tp[(size_t)(t + 2) * 192];
            float4 d = tp[(size_t)(t + 3) * 192];
            s0.x += a.x; s0.y += a.y; s0.z += a.z; s0.w += a.w;
            s1.x += b.x; s1.y += b.y; s1.z += b.z; s1.w += b.w;
            s2.x += c.x; s2.y += c.y; s2.z += c.z; s2.w += c.w;
            s3.x += d.x; s3.y += d.y; s3.z += d.z; s3.w += d.w;
        }
        for (; t < Sm1; t++) {
            float4 a = tp[(size_t)t * 192];
            s0.x += a.x; s0.y += a.y; s0.z += a.z; s0.w += a.w;
        }
        float4 s = make_float4(s0.x + s1.x + s2.x + s3.x, s0.y + s1.y + s2.y + s3.y,
                               s0.z + s1.z + s2.z + s3.z, s0.w + s1.w + s2.w + s3.w);
        *(float4*)&sumtok[tid * 4] = s;
    }
    __syncthreads();

    const int warp = tid >> 5, lane = tid & 31;
    {
        float part[N_EXP];
#pragma unroll
        for (int e = 0; e < N_EXP; e++) part[e] = 0.f;
        for (int c = tid; c < D_IN; c += 256) {
            float cl = cls[(size_t)i * D_IN + c];
            float s = sumtok[c];
#pragma unroll
            for (int e = 0; e < N_EXP; e++)
                part[e] += cl * WcCls[c * N_EXP + e] + s * WcTok[c * N_EXP + e];
        }
#pragma unroll
        for (int o = 16; o; o >>= 1)
#pragma unroll
            for (int e = 0; e < N_EXP; e++)
                part[e] += __shfl_down_sync(0xffffffffu, part[e], o);
        if (lane == 0)
#pragma unroll
            for (int e = 0; e < N_EXP; e++) red[warp][e] = part[e];
    }
    __syncthreads();
    if (tid < N_EXP) {
        float l = 0.f;
        for (int wq = 0; wq < 8; wq++) l += red[wq][tid];
        logits[tid] = l / (float)(Sm1 + 1) + bt[tid];
    }
    __syncthreads();
    if (tid == 0) {
        int b0 = 0;
        for (int e = 1; e < N_EXP; e++)
            if (logits[e] > logits[b0]) b0 = e;
        int b1 = (b0 == 0) ? 1 : 0;
        for (int e = 0; e < N_EXP; e++)
            if (e != b0 && logits[e] > logits[b1]) b1 = e;
        float e1v = expf(logits[b1] - logits[b0]);
        float inv = 1.0f / (1.0f + e1v);
        eidx[i] = make_int2(b0, b1);
        ew[i] = make_float2(inv, e1v * inv);
    }
}

// ------------- cross attention: tokens resident in dynamic smem -------------
__global__ __launch_bounds__(256) void cross_kernel(
    const float* __restrict__ moe_out, int S, float* __restrict__ ctx)
{
    extern __shared__ float tokbuf[];
    __shared__ float prob[64];
    const int i = blockIdx.x;
    const int tid = threadIdx.x;
    const float* base = moe_out + (size_t)i * S * H_DIM;

    {
        const float4* src = (const float4*)base;
        float4* dst = (float4*)tokbuf;
        const int n4 = S * (H_DIM / 4);
        for (int idx = tid; idx < n4; idx += 256) dst[idx] = src[idx];
    }
    __syncthreads();

    const int nt = S - 1;
    const int warp = tid >> 5, lane = tid & 31;
    for (int s = warp; s < nt; s += 8) {
        const float4* tr = (const float4*)(tokbuf + (s + 1) * H_DIM);
        const float4* cl = (const float4*)tokbuf;
        float p = 0.f;
#pragma unroll
        for (int q = 0; q < 4; q++) {
            float4 a = cl[lane + 32 * q];
            float4 b = tr[lane + 32 * q];
            p += a.x * b.x + a.y * b.y + a.z * b.z + a.w * b.w;
        }
#pragma unroll
        for (int o = 16; o; o >>= 1) p += __shfl_down_sync(0xffffffffu, p, o);
        if (lane == 0) prob[s] = p;
    }
    __syncthreads();

    if (tid == 0) {
        float mx = -1e30f;
        for (int s = 0; s < nt; s++) mx = fmaxf(mx, prob[s]);
        float sum = 0.f;
        for (int s = 0; s < nt; s++) { float e = expf(prob[s] - mx); prob[s] = e; sum += e; }
        float inv = 1.0f / sum;
        for (int s = 0; s < nt; s++) prob[s] *= inv;
    }
    __syncthreads();

    float2 acc = make_float2(0.f, 0.f);
    const float2* b2 = (const float2*)(tokbuf + H_DIM) + tid;
#pragma unroll 4
    for (int s = 0; s < nt; s++) {
        float2 v = b2[(size_t)s * (H_DIM / 2)];
        float pw = prob[s];
        acc.x += pw * v.x; acc.y += pw * v.y;
    }
    ((float2*)(ctx + (size_t)i * H_DIM))[tid] = acc;
}

// --------------------------- gate + residual + LN ---------------------------
__global__ __launch_bounds__(256) void gate_ln_kernel(
    const float* __restrict__ ori, const float* __restrict__ ctx,
    const float* __restrict__ Wg, const float* __restrict__ bg,
    const float* __restrict__ ls, const float* __restrict__ lb,
    float* __restrict__ out, int gate_from_ctx)
{
    const int i = blockIdx.x;
    __shared__ float v[H_DIM];
    __shared__ float red[256];
    const int tid = threadIdx.x;
    const float* orow = ori + (size_t)i * H_DIM;
    const float* crow = ctx + (size_t)i * H_DIM;

    float p = 0.f;
    for (int c = tid; c < H_DIM; c += 256) {
        float gs = gate_from_ctx ? crow[c] : orow[c];
        p += gs * Wg[c];
    }
    red[tid] = p; __syncthreads();
    for (int o = 128; o; o >>= 1) { if (tid < o) red[tid] += red[tid + o]; __syncthreads(); }
    float gate = tanhf(red[0] + bg[0]);
    __syncthreads();

    float sum = 0.f;
    for (int c = tid; c < H_DIM; c += 256) {
        float val = orow[c] * gate + crow[c];
        v[c] = val; sum += val;
    }
    red[tid] = sum; __syncthreads();
    for (int o = 128; o; o >>= 1) { if (tid < o) red[tid] += red[tid + o]; __syncthreads(); }
    float mean = red[0] / (float)H_DIM;
    __syncthreads();

    float var = 0.f;
    for (int c = tid; c < H_DIM; c += 256) { float d = v[c] - mean; var += d * d; }
    red[tid] = var; __syncthreads();
    for (int o = 128; o; o >>= 1) { if (tid < o) red[tid] += red[tid + o]; __syncthreads(); }
    float rstd = rsqrtf(red[0] / (float)H_DIM + 1e-5f);

    for (int c = tid; c < H_DIM; c += 256)
        out[(size_t)i * H_DIM + c] = (v[c] - mean) * rstd * ls[c] + lb[c];
}

// -------------------------------- final score -------------------------------
__global__ __launch_bounds__(256) void score_kernel(
    const float* __restrict__ mti, const float* __restrict__ eti,
    const float* __restrict__ mit, const float* __restrict__ eit,
    float* __restrict__ out)
{
    __shared__ float As[8][64];
    __shared__ float Bs[8][64];
    const int n0 = blockIdx.x * 64;
    const int b0 = blockIdx.y * 64;
    const int tid = threadIdx.x;
    const int tx = tid & 15, ty = tid >> 4;
    const int lrow = tid >> 2, lcol = (tid & 3) * 2;

    float acc[4][4];
#pragma unroll
    for (int q = 0; q < 4; q++)
#pragma unroll
        for (int r = 0; r < 4; r++) acc[q][r] = 0.f;

#pragma unroll
    for (int pass = 0; pass < 2; pass++) {
        const float* A = pass ? mit : mti;
        const float* B = pass ? eit : eti;
        for (int k0 = 0; k0 < H_DIM; k0 += 8) {
            float2 av = *(const float2*)(A + (size_t)(b0 + lrow) * H_DIM + k0 + lcol);
            As[lcol][lrow] = av.x; As[lcol + 1][lrow] = av.y;
            float2 bv = *(const float2*)(B + (size_t)(n0 + lrow) * H_DIM + k0 + lcol);
            Bs[lcol][lrow] = bv.x; Bs[lcol + 1][lrow] = bv.y;
            __syncthreads();
#pragma unroll
            for (int k = 0; k < 8; k++) {
                float a[4], b[4];
#pragma unroll
                for (int q = 0; q < 4; q++) a[q] = As[k][ty * 4 + q];
#pragma unroll
                for (int q = 0; q < 4; q++) b[q] = Bs[k][tx * 4 + q];
#pragma unroll
                for (int q = 0; q < 4; q++)
#pragma unroll
                    for (int r = 0; r < 4; r++) acc[q][r] += a[q] * b[r];
            }
            __syncthreads();
        }
    }
#pragma unroll
    for (int q = 0; q < 4; q++)
#pragma unroll
        for (int r = 0; r < 4; r++)
            out[(size_t)(b0 + ty * 4 + q) * N_ENT + (n0 + tx * 4 + r)] = 0.5f * acc[q][r];
}

// ---------------------------------- launch ----------------------------------
extern "C" void kernel_launch(void* const* d_in, const int* in_sizes, int n_in,
                              void* d_out, int out_size)
{
    const float* etc_in = (const float*)d_in[0];
    const float* ett_in = (const float*)d_in[1];
    const float* mtc_in = (const float*)d_in[2];
    const float* mtt_in = (const float*)d_in[3];
    const float* eic_in = (const float*)d_in[4];
    const float* eit_in = (const float*)d_in[5];
    const float* mic_in = (const float*)d_in[6];
    const float* mit_in = (const float*)d_in[7];
    const float* W_text = (const float*)d_in[8];
    const float* b_text = (const float*)d_in[9];
    const float* W_img  = (const float*)d_in[10];
    const float* b_img  = (const float*)d_in[11];
    const float* W_gate = (const float*)d_in[12];
    const float* b_gate = (const float*)d_in[13];
    const float* ln_s   = (const float*)d_in[14];
    const float* ln_b   = (const float*)d_in[15];
    const float* W_rout = (const float*)d_in[16];
    const float* b_rout = (const float*)d_in[17];
    const float* W_exp  = (const float*)d_in[18];
    const float* b_exp  = (const float*)d_in[19];
    float* out = (float*)d_out;

    float *p_etc, *p_eic, *p_mtc, *p_mic, *p_ett, *p_eit, *p_mtt, *p_mit;
    float *p_etim, *p_mtim, *p_eitm, *p_mitm;
    float *p_ctx0, *p_ctx1, *p_ctx2, *p_ctx3;
    float *p_feti, *p_fmti, *p_feit, *p_fmit;
    float *p_wct, *p_wci, *p_bt;
    uint32_t *p_wh, *p_wl;
    int2* p_eidx; float2* p_ew;
    cudaGetSymbolAddress((void**)&p_etc, g_etc);
    cudaGetSymbolAddress((void**)&p_eic, g_eic);
    cudaGetSymbolAddress((void**)&p_mtc, g_mtc);
    cudaGetSymbolAddress((void**)&p_mic, g_mic);
    cudaGetSymbolAddress((void**)&p_ett, g_ett);
    cudaGetSymbolAddress((void**)&p_eit, g_eit);
    cudaGetSymbolAddress((void**)&p_mtt, g_mtt);
    cudaGetSymbolAddress((void**)&p_mit, g_mit);
    cudaGetSymbolAddress((void**)&p_etim, g_eti_m);
    cudaGetSymbolAddress((void**)&p_mtim, g_mti_m);
    cudaGetSymbolAddress((void**)&p_eitm, g_eit_m);
    cudaGetSymbolAddress((void**)&p_mitm, g_mit_m);
    cudaGetSymbolAddress((void**)&p_ctx0, g_ctx0);
    cudaGetSymbolAddress((void**)&p_ctx1, g_ctx1);
    cudaGetSymbolAddress((void**)&p_ctx2, g_ctx2);
    cudaGetSymbolAddress((void**)&p_ctx3, g_ctx3);
    cudaGetSymbolAddress((void**)&p_feti, g_fe_ti);
    cudaGetSymbolAddress((void**)&p_fmti, g_fm_ti);
    cudaGetSymbolAddress((void**)&p_feit, g_fe_it);
    cudaGetSymbolAddress((void**)&p_fmit, g_fm_it);
    cudaGetSymbolAddress((void**)&p_wct, g_wc_text);
    cudaGetSymbolAddress((void**)&p_wci, g_wc_img);
    cudaGetSymbolAddress((void**)&p_bt, g_bterm);
    cudaGetSymbolAddress((void**)&p_wh, g_wsp_h);
    cudaGetSymbolAddress((void**)&p_wl, g_wsp_l);
    cudaGetSymbolAddress((void**)&p_eidx, g_eidx);
    cudaGetSymbolAddress((void**)&p_ew,   g_ew);

    const int CROSS_SMEM = 65 * H_DIM * 4;
    cudaFuncSetAttribute(cross_kernel, cudaFuncAttributeMaxDynamicSharedMemorySize, CROSS_SMEM);

    dim3 blk(256);
    dim3 blkg(128);

    // 1: prep (router fold + proj weight pre-split)
    combine_w_kernel<<<(2 * WSP_SZ + 255) / 256, blk>>>(W_text, W_img, W_rout,
                                                        p_wct, p_wci, p_wh, p_wl);
    // 2: bias terms
    bterm_kernel<<<1, 32>>>(b_text, b_img, W_rout, b_rout, p_bt);

    // 3: first big router
    router2_kernel<<<N_ENT, blk>>>(eic_in, ett_in, T_TOK, p_wci, p_wct, p_bt,
                                   p_eidx + 0 * N_ENT, p_ew + 0 * N_ENT);

    // 4: big ett projection — positioned for ncu capture
    proj_tc<<<dim3(4, N_ENT * T_TOK / 128), blkg>>>(ett_in, p_wh, p_wl, b_text, p_ett, N_ENT * T_TOK);

    // remaining routers
    router2_kernel<<<BATCH, blk>>>(mic_in, mtt_in, T_TOK, p_wci, p_wct, p_bt,
                                   p_eidx + 1 * N_ENT, p_ew + 1 * N_ENT);
    router2_kernel<<<N_ENT, blk>>>(etc_in, eit_in, P_TOK, p_wct, p_wci, p_bt + N_EXP,
                                   p_eidx + 2 * N_ENT, p_ew + 2 * N_ENT);
    router2_kernel<<<BATCH, blk>>>(mtc_in, mit_in, P_TOK, p_wct, p_wci, p_bt + N_EXP,
                                   p_eidx + 3 * N_ENT, p_ew + 3 * N_ENT);

    // remaining projections: fused cls pairs + token tensors
    proj_cls_tc<<<dim3(4, N_ENT / 128, 2), blkg>>>(etc_in, eic_in, p_wh, p_wl,
                                                   b_text, b_img, p_etc, p_eic);
    proj_cls_tc<<<dim3(4, BATCH / 128, 2), blkg>>>(mtc_in, mic_in, p_wh, p_wl,
                                                   b_text, b_img, p_mtc, p_mic);
    proj_tc<<<dim3(4, BATCH * T_TOK / 128), blkg>>>(mtt_in, p_wh, p_wl, b_text, p_mtt, BATCH * T_TOK);
    proj_tc<<<dim3(4, N_ENT * P_TOK / 128), blkg>>>(eit_in, p_wh + WSP_SZ, p_wl + WSP_SZ, b_img, p_eit, N_ENT * P_TOK);
    proj_tc<<<dim3(4, BATCH * P_TOK / 128), blkg>>>(mit_in, p_wh + WSP_SZ, p_wl + WSP_SZ, b_img, p_mit, BATCH * P_TOK);

    // MoE GEMMs (combined expert pair, bf16x3)
    moe2_tc<<<dim3(2, 1, N_ENT), blkg>>>(p_etc, p_eit, W_exp, b_exp,
                                         p_eidx + 0 * N_ENT, p_ew + 0 * N_ENT, p_etim);
    moe2_tc<<<dim3(2, 1, BATCH), blkg>>>(p_mtc, p_mit, W_exp, b_exp,
                                         p_eidx + 1 * N_ENT, p_ew + 1 * N_ENT, p_mtim);
    moe3_tc<<<dim3(4, 1, N_ENT), blkg>>>(p_eic, p_ett, W_exp, b_exp,
                                         p_eidx + 2 * N_ENT, p_ew + 2 * N_ENT, p_eitm);
    moe3_tc<<<dim3(4, 1, BATCH), blkg>>>(p_mic, p_mtt, W_exp, b_exp,
                                         p_eidx + 3 * N_ENT, p_ew + 3 * N_ENT, p_mitm);

    // cross attention (tokens smem-resident)
    cross_kernel<<<N_ENT, blk, 50 * H_DIM * 4>>>(p_etim, 50, p_ctx0);
    cross_kernel<<<BATCH, blk, 50 * H_DIM * 4>>>(p_mtim, 50, p_ctx1);
    cross_kernel<<<N_ENT, blk, 65 * H_DIM * 4>>>(p_eitm, 65, p_ctx2);
    cross_kernel<<<BATCH, blk, 65 * H_DIM * 4>>>(p_mitm, 65, p_ctx3);

    // gate + residual + LN
    gate_ln_kernel<<<N_ENT, blk>>>(p_etc, p_ctx0, W_gate, b_gate, ln_s, ln_b, p_feti, 1);
    gate_ln_kernel<<<BATCH, blk>>>(p_mtc, p_ctx1, W_gate, b_gate, ln_s, ln_b, p_fmti, 0);
    gate_ln_kernel<<<N_ENT, blk>>>(p_eic, p_ctx2, W_gate, b_gate, ln_s, ln_b, p_feit, 1);
    gate_ln_kernel<<<BATCH, blk>>>(p_mic, p_ctx3, W_gate, b_gate, ln_s, ln_b, p_fmit, 0);

    // final score
    score_kernel<<<dim3(N_ENT / 64, BATCH / 64), blk>>>(p_fmti, p_feti, p_fmit, p_feit, out);
}

// round 16
// speedup vs baseline: 1.2327x; 1.1026x over previous
#include <cuda_runtime.h>
#include <cuda_bf16.h>
#include <math.h>
#include <stdint.h>

#define N_ENT 1024
#define BATCH 128
#define T_TOK 64
#define P_TOK 49
#define D_IN 768
#define H_DIM 512
#define N_EXP 8
#define NKP (D_IN / 2)
#define WSP_SZ (NKP * H_DIM)

// ----------------------------- static scratch ------------------------------
__device__ float g_etc[N_ENT * H_DIM];
__device__ float g_eic[N_ENT * H_DIM];
__device__ float g_mtc[BATCH * H_DIM];
__device__ float g_mic[BATCH * H_DIM];
__device__ float g_ett[N_ENT * T_TOK * H_DIM];
__device__ float g_eit[N_ENT * P_TOK * H_DIM];
__device__ float g_mtt[BATCH * T_TOK * H_DIM];
__device__ float g_mit[BATCH * P_TOK * H_DIM];

__device__ float g_eti_m[N_ENT * 50 * H_DIM];
__device__ float g_mti_m[BATCH * 50 * H_DIM];
__device__ float g_eit_m[N_ENT * 65 * H_DIM];
__device__ float g_mit_m[BATCH * 65 * H_DIM];

__device__ int2   g_eidx[4][N_ENT];
__device__ float2 g_ew[4][N_ENT];

__device__ float g_ctx0[N_ENT * H_DIM];
__device__ float g_ctx1[BATCH * H_DIM];
__device__ float g_ctx2[N_ENT * H_DIM];
__device__ float g_ctx3[BATCH * H_DIM];

__device__ float g_fe_ti[N_ENT * H_DIM];
__device__ float g_fm_ti[BATCH * H_DIM];
__device__ float g_fe_it[N_ENT * H_DIM];
__device__ float g_fm_it[BATCH * H_DIM];

__device__ float g_wc_text[D_IN * N_EXP];
__device__ float g_wc_img[D_IN * N_EXP];
__device__ float g_bterm[2 * N_EXP];

// pre-split projection weights: packed bf16 pairs (k, k+1), [pair][n]
__device__ uint32_t g_wsp_h[2 * WSP_SZ];
__device__ uint32_t g_wsp_l[2 * WSP_SZ];

// --------------------------- bf16 split helpers -----------------------------
__device__ __forceinline__ void split_bf16x2(float a, float b, uint32_t& h, uint32_t& l)
{
    __nv_bfloat162 hp = __floats2bfloat162_rn(a, b);
    float ra = a - __bfloat162float(hp.x);
    float rb = b - __bfloat162float(hp.y);
    __nv_bfloat162 lp = __floats2bfloat162_rn(ra, rb);
    h = *(uint32_t*)&hp;
    l = *(uint32_t*)&lp;
}

__device__ __forceinline__ void splitB4(float4 r0, float4 r1, uint4& h, uint4& l)
{
    split_bf16x2(r0.x, r1.x, h.x, l.x);
    split_bf16x2(r0.y, r1.y, h.y, l.y);
    split_bf16x2(r0.z, r1.z, h.z, l.z);
    split_bf16x2(r0.w, r1.w, h.w, l.w);
}

__device__ __forceinline__ void mma16(float* c, const uint32_t* a, const uint32_t* b)
{
    asm volatile(
        "mma.sync.aligned.m16n8k16.row.col.f32.bf16.bf16.f32 "
        "{%0,%1,%2,%3}, {%4,%5,%6,%7}, {%8,%9}, {%0,%1,%2,%3};"
        : "+f"(c[0]), "+f"(c[1]), "+f"(c[2]), "+f"(c[3])
        : "r"(a[0]), "r"(a[1]), "r"(a[2]), "r"(a[3]), "r"(b[0]), "r"(b[1]));
}

#define ASTRP 12
#define BSTRP 136
#define BSTRP2 264

// ------------------ proj body (bf16x3), smem passed in ---------------------
__device__ __forceinline__ void proj_body(
    const float* __restrict__ A,
    const uint32_t* __restrict__ Wh, const uint32_t* __restrict__ Wl,
    const float* __restrict__ bias, float* __restrict__ C,
    int row0, int col0, void* smu)
{
    uint32_t* AsH = (uint32_t*)smu;
    uint32_t* AsL = AsH + 128 * ASTRP;
    uint32_t* BsH = AsL + 128 * ASTRP;
    uint32_t* BsL = BsH + 8 * BSTRP;

    const int tid = threadIdx.x;
    const int warp = tid >> 5, lane = tid & 31;
    const int wm = warp >> 1, wn = warp & 1;
    const int gid = lane >> 2, tig = lane & 3;
    const int bk = tid >> 4;
    const int nc = (tid & 15) * 8;

    float acc[4][8][4];
#pragma unroll
    for (int a = 0; a < 4; a++)
#pragma unroll
        for (int b = 0; b < 8; b++)
#pragma unroll
            for (int c = 0; c < 4; c++) acc[a][b][c] = 0.f;

    const float* Arow = A + (size_t)(row0 + tid) * D_IN;

    for (int kb = 0; kb < D_IN / 16; kb++) {
        const int k0 = kb * 16;
#pragma unroll
        for (int q = 0; q < 4; q++) {
            float4 v = *(const float4*)(Arow + k0 + q * 4);
            uint32_t h0, l0, h1, l1;
            split_bf16x2(v.x, v.y, h0, l0);
            split_bf16x2(v.z, v.w, h1, l1);
            *(uint2*)&AsH[tid * ASTRP + q * 2] = make_uint2(h0, h1);
            *(uint2*)&AsL[tid * ASTRP + q * 2] = make_uint2(l0, l1);
        }
        {
            size_t off = (size_t)(kb * 8 + bk) * H_DIM + col0 + nc;
            *(uint4*)&BsH[bk * BSTRP + nc]     = *(const uint4*)(Wh + off);
            *(uint4*)&BsH[bk * BSTRP + nc + 4] = *(const uint4*)(Wh + off + 4);
            *(uint4*)&BsL[bk * BSTRP + nc]     = *(const uint4*)(Wl + off);
            *(uint4*)&BsL[bk * BSTRP + nc + 4] = *(const uint4*)(Wl + off + 4);
        }
        __syncthreads();

        uint32_t ah[4][4], al[4][4], bh[8][2], bl[8][2];
#pragma unroll
        for (int mt = 0; mt < 4; mt++) {
            int r = (wm * 64 + mt * 16 + gid) * ASTRP;
            ah[mt][0] = AsH[r + tig];     ah[mt][1] = AsH[r + 8 * ASTRP + tig];
            ah[mt][2] = AsH[r + tig + 4]; ah[mt][3] = AsH[r + 8 * ASTRP + tig + 4];
            al[mt][0] = AsL[r + tig];     al[mt][1] = AsL[r + 8 * ASTRP + tig];
            al[mt][2] = AsL[r + tig + 4]; al[mt][3] = AsL[r + 8 * ASTRP + tig + 4];
        }
#pragma unroll
        for (int nt = 0; nt < 8; nt++) {
            int c = wn * 64 + nt * 8 + gid;
            bh[nt][0] = BsH[tig * BSTRP + c]; bh[nt][1] = BsH[(tig + 4) * BSTRP + c];
            bl[nt][0] = BsL[tig * BSTRP + c]; bl[nt][1] = BsL[(tig + 4) * BSTRP + c];
        }
#pragma unroll
        for (int mt = 0; mt < 4; mt++)
#pragma unroll
            for (int nt = 0; nt < 8; nt++) mma16(acc[mt][nt], ah[mt], bh[nt]);
#pragma unroll
        for (int mt = 0; mt < 4; mt++)
#pragma unroll
            for (int nt = 0; nt < 8; nt++) mma16(acc[mt][nt], ah[mt], bl[nt]);
#pragma unroll
        for (int mt = 0; mt < 4; mt++)
#pragma unroll
            for (int nt = 0; nt < 8; nt++) mma16(acc[mt][nt], al[mt], bh[nt]);
        __syncthreads();
    }

#pragma unroll
    for (int mt = 0; mt < 4; mt++) {
        int m = row0 + wm * 64 + mt * 16 + gid;
#pragma unroll
        for (int nt = 0; nt < 8; nt++) {
            int n = col0 + wn * 64 + nt * 8 + tig * 2;
            float2 bv = *(const float2*)(bias + n);
            *(float2*)(C + (size_t)m * H_DIM + n) =
                make_float2(acc[mt][nt][0] + bv.x, acc[mt][nt][1] + bv.y);
            *(float2*)(C + (size_t)(m + 8) * H_DIM + n) =
                make_float2(acc[mt][nt][2] + bv.x, acc[mt][nt][3] + bv.y);
        }
    }
}

// ------------------ router body (128 threads), smem passed in ---------------
__device__ __forceinline__ void router_body(
    const float* __restrict__ cls, const float* __restrict__ tok, int Sm1,
    const float* __restrict__ WcCls, const float* __restrict__ WcTok,
    const float* __restrict__ bt,
    int2* __restrict__ eidx, float2* __restrict__ ew, int i, void* smu)
{
    float* sumtok = (float*)smu;            // 768
    float* red    = sumtok + D_IN;          // [4][8]
    float* logits = red + 32;               // 8
    const int tid = threadIdx.x;

    // stage 1: sum of Sm1 token rows (192 float4 cols, 2 passes of 128 threads)
#pragma unroll
    for (int p = 0; p < 2; p++) {
        int idx = tid + p * 128;
        if (idx < 192) {
            const float4* tp = (const float4*)(tok + (size_t)i * Sm1 * D_IN) + idx;
            float4 s0 = make_float4(0.f, 0.f, 0.f, 0.f), s1 = s0, s2 = s0, s3 = s0;
            int t = 0;
            for (; t + 4 <= Sm1; t += 4) {
                float4 a = tp[(size_t)(t + 0) * 192];
                float4 b = tp[(size_t)(t + 1) * 192];
                float4 c = tp[(size_t)(t + 2) * 192];
                float4 d = tp[(size_t)(t + 3) * 192];
                s0.x += a.x; s0.y += a.y; s0.z += a.z; s0.w += a.w;
                s1.x += b.x; s1.y += b.y; s1.z += b.z; s1.w += b.w;
                s2.x += c.x; s2.y += c.y; s2.z += c.z; s2.w += c.w;
                s3.x += d.x; s3.y += d.y; s3.z += d.z; s3.w += d.w;
            }
            for (; t < Sm1; t++) {
                float4 a = tp[(size_t)t * 192];
                s0.x += a.x; s0.y += a.y; s0.z += a.z; s0.w += a.w;
            }
            float4 s = make_float4(s0.x + s1.x + s2.x + s3.x, s0.y + s1.y + s2.y + s3.y,
                                   s0.z + s1.z + s2.z + s3.z, s0.w + s1.w + s2.w + s3.w);
            *(float4*)&sumtok[idx * 4] = s;
        }
    }
    __syncthreads();

    // stage 2: logits
    const int warp = tid >> 5, lane = tid & 31;
    {
        float part[N_EXP];
#pragma unroll
        for (int e = 0; e < N_EXP; e++) part[e] = 0.f;
        for (int c = tid; c < D_IN; c += 128) {
            float cl = cls[(size_t)i * D_IN + c];
            float s = sumtok[c];
#pragma unroll
            for (int e = 0; e < N_EXP; e++)
                part[e] += cl * WcCls[c * N_EXP + e] + s * WcTok[c * N_EXP + e];
        }
#pragma unroll
        for (int o = 16; o; o >>= 1)
#pragma unroll
            for (int e = 0; e < N_EXP; e++)
                part[e] += __shfl_down_sync(0xffffffffu, part[e], o);
        if (lane == 0)
#pragma unroll
            for (int e = 0; e < N_EXP; e++) red[warp * N_EXP + e] = part[e];
    }
    __syncthreads();
    if (tid < N_EXP) {
        float l = 0.f;
        for (int wq = 0; wq < 4; wq++) l += red[wq * N_EXP + tid];
        logits[tid] = l / (float)(Sm1 + 1) + bt[tid];
    }
    __syncthreads();
    if (tid == 0) {
        int b0 = 0;
        for (int e = 1; e < N_EXP; e++)
            if (logits[e] > logits[b0]) b0 = e;
        int b1 = (b0 == 0) ? 1 : 0;
        for (int e = 0; e < N_EXP; e++)
            if (e != b0 && logits[e] > logits[b1]) b1 = e;
        float e1v = expf(logits[b1] - logits[b0]);
        float inv = 1.0f / (1.0f + e1v);
        eidx[i] = make_int2(b0, b1);
        ew[i] = make_float2(inv, e1v * inv);
    }
}

// -------- stage-1 mega kernel: 4 routers + 8 projections, one launch --------
// block roles: [0,2304) routers; [2304,6444) proj tiles (col fastest per job).
#define R_TOTAL 2304
#define PJ0 2048   // ett  (512 rowblocks)
#define PJ1 1568   // eit  (392)
#define PJ2 256    // mtt  (64)
#define PJ3 196    // mit  (49)
#define PJ4 32     // etc  (8)
#define PJ5 32     // eic  (8)
#define PJ6 4      // mtc  (1)
#define PJ7 4      // mic  (1)
#define MEGA_GRID (R_TOTAL + PJ0 + PJ1 + PJ2 + PJ3 + PJ4 + PJ5 + PJ6 + PJ7)

__global__ __launch_bounds__(128, 2) void stage1_mega(
    const float* __restrict__ etc_in, const float* __restrict__ ett_in,
    const float* __restrict__ mtc_in, const float* __restrict__ mtt_in,
    const float* __restrict__ eic_in, const float* __restrict__ eit_in,
    const float* __restrict__ mic_in, const float* __restrict__ mit_in,
    const uint32_t* __restrict__ Wh, const uint32_t* __restrict__ Wl,
    const float* __restrict__ b_text, const float* __restrict__ b_img,
    const float* __restrict__ WcT, const float* __restrict__ WcI,
    const float* __restrict__ bt,
    float* __restrict__ p_etc, float* __restrict__ p_ett,
    float* __restrict__ p_mtc, float* __restrict__ p_mtt,
    float* __restrict__ p_eic, float* __restrict__ p_eit,
    float* __restrict__ p_mic, float* __restrict__ p_mit,
    int2* __restrict__ eidx, float2* __restrict__ ew)
{
    __shared__ __align__(16) char smu[(2 * 128 * ASTRP + 2 * 8 * BSTRP) * 4];
    const int b = blockIdx.x;

    if (b < R_TOTAL) {
        if (b < 1024)
            router_body(eic_in, ett_in, T_TOK, WcI, WcT, bt,
                        eidx, ew, b, smu);
        else if (b < 1152)
            router_body(mic_in, mtt_in, T_TOK, WcI, WcT, bt,
                        eidx + N_ENT, ew + N_ENT, b - 1024, smu);
        else if (b < 2176)
            router_body(etc_in, eit_in, P_TOK, WcT, WcI, bt + N_EXP,
                        eidx + 2 * N_ENT, ew + 2 * N_ENT, b - 1152, smu);
        else
            router_body(mtc_in, mit_in, P_TOK, WcT, WcI, bt + N_EXP,
                        eidx + 3 * N_ENT, ew + 3 * N_ENT, b - 2176, smu);
        return;
    }

    int q = b - R_TOTAL;
    const float* A; const uint32_t *wh, *wl; const float* bias; float* C;
    if (q < PJ0)                       { A = ett_in; wh = Wh; wl = Wl; bias = b_text; C = p_ett; }
    else if ((q -= PJ0) < PJ1)         { A = eit_in; wh = Wh + WSP_SZ; wl = Wl + WSP_SZ; bias = b_img; C = p_eit; }
    else if ((q -= PJ1) < PJ2)         { A = mtt_in; wh = Wh; wl = Wl; bias = b_text; C = p_mtt; }
    else if ((q -= PJ2) < PJ3)         { A = mit_in; wh = Wh + WSP_SZ; wl = Wl + WSP_SZ; bias = b_img; C = p_mit; }
    else if ((q -= PJ3) < PJ4)         { A = etc_in; wh = Wh; wl = Wl; bias = b_text; C = p_etc; }
    else if ((q -= PJ4) < PJ5)         { A = eic_in; wh = Wh + WSP_SZ; wl = Wl + WSP_SZ; bias = b_img; C = p_eic; }
    else if ((q -= PJ5) < PJ6)         { A = mtc_in; wh = Wh; wl = Wl; bias = b_text; C = p_mtc; }
    else                { q -= PJ6;      A = mic_in; wh = Wh + WSP_SZ; wl = Wl + WSP_SZ; bias = b_img; C = p_mic; }

    proj_body(A, wh, wl, bias, C, (q >> 2) * 128, (q & 3) * 128, smu);
}

// -------- MoE S=50 (bf16x3): block 64x256, 4 warps of 64x64 ----------------
__global__ __launch_bounds__(128, 2) void moe2_tc(
    const float* __restrict__ cls, const float* __restrict__ tok,
    const float* __restrict__ We, const float* __restrict__ be,
    const int2* __restrict__ eidx, const float2* __restrict__ ew,
    float* __restrict__ out)
{
    const int S = 50;
    __shared__ uint32_t AsH[64 * ASTRP], AsL[64 * ASTRP];
    __shared__ uint32_t BsH[8 * BSTRP2], BsL[8 * BSTRP2];

    const int i = blockIdx.z;
    const int col0 = blockIdx.x * 256;
    const int2 e = eidx[i];
    const float2 w = ew[i];
    const float* W0 = We + (size_t)e.x * H_DIM * H_DIM;
    const float* W1 = We + (size_t)e.y * H_DIM * H_DIM;

    const int tid = threadIdx.x;
    const int warp = tid >> 5, lane = tid & 31;
    const int wn = warp;
    const int gid = lane >> 2, tig = lane & 3;
    const int bk = tid >> 4;
    const int nc = (tid & 15) * 16;
    const int arow = tid & 63, ahalf = tid >> 6;

    const float* rp = nullptr;
    if (arow < S)
        rp = (arow == 0) ? (cls + (size_t)i * H_DIM)
                         : (tok + ((size_t)i * (S - 1) + (arow - 1)) * H_DIM);

    float acc[4][8][4];
#pragma unroll
    for (int a = 0; a < 4; a++)
#pragma unroll
        for (int b = 0; b < 8; b++)
#pragma unroll
            for (int c = 0; c < 4; c++) acc[a][b][c] = 0.f;

    for (int kb = 0; kb < H_DIM / 16; kb++) {
        const int k0 = kb * 16;
#pragma unroll
        for (int q = 0; q < 2; q++) {
            float4 v = make_float4(0.f, 0.f, 0.f, 0.f);
            if (rp) v = *(const float4*)(rp + k0 + ahalf * 8 + q * 4);
            uint32_t h0, l0, h1, l1;
            split_bf16x2(v.x, v.y, h0, l0);
            split_bf16x2(v.z, v.w, h1, l1);
            *(uint2*)&AsH[arow * ASTRP + ahalf * 4 + q * 2] = make_uint2(h0, h1);
            *(uint2*)&AsL[arow * ASTRP + ahalf * 4 + q * 2] = make_uint2(l0, l1);
        }
        {
            size_t o0 = (size_t)(k0 + 2 * bk) * H_DIM + col0 + nc;
#pragma unroll
            for (int q = 0; q < 4; q++) {
                float4 a0 = *(const float4*)(W0 + o0 + q * 4);
                float4 b0 = *(const float4*)(W1 + o0 + q * 4);
                float4 a1 = *(const float4*)(W0 + o0 + H_DIM + q * 4);
                float4 b1 = *(const float4*)(W1 + o0 + H_DIM + q * 4);
                float4 r0 = make_float4(w.x * a0.x + w.y * b0.x, w.x * a0.y + w.y * b0.y,
                                        w.x * a0.z + w.y * b0.z, w.x * a0.w + w.y * b0.w);
                float4 r1 = make_float4(w.x * a1.x + w.y * b1.x, w.x * a1.y + w.y * b1.y,
                                        w.x * a1.z + w.y * b1.z, w.x * a1.w + w.y * b1.w);
                uint4 h, l;
                splitB4(r0, r1, h, l);
                *(uint4*)&BsH[bk * BSTRP2 + nc + q * 4] = h;
                *(uint4*)&BsL[bk * BSTRP2 + nc + q * 4] = l;
            }
        }
        __syncthreads();

        uint32_t ah[4][4], al[4][4], bh[8][2], bl[8][2];
#pragma unroll
        for (int mt = 0; mt < 4; mt++) {
            int r = (mt * 16 + gid) * ASTRP;
            ah[mt][0] = AsH[r + tig];     ah[mt][1] = AsH[r + 8 * ASTRP + tig];
            ah[mt][2] = AsH[r + tig + 4]; ah[mt][3] = AsH[r + 8 * ASTRP + tig + 4];
            al[mt][0] = AsL[r + tig];     al[mt][1] = AsL[r + 8 * ASTRP + tig];
            al[mt][2] = AsL[r + tig + 4]; al[mt][3] = AsL[r + 8 * ASTRP + tig + 4];
        }
#pragma unroll
        for (int nt = 0; nt < 8; nt++) {
            int c = wn * 64 + nt * 8 + gid;
            bh[nt][0] = BsH[tig * BSTRP2 + c]; bh[nt][1] = BsH[(tig + 4) * BSTRP2 + c];
            bl[nt][0] = BsL[tig * BSTRP2 + c]; bl[nt][1] = BsL[(tig + 4) * BSTRP2 + c];
        }
#pragma unroll
        for (int mt = 0; mt < 4; mt++)
#pragma unroll
            for (int nt = 0; nt < 8; nt++) mma16(acc[mt][nt], ah[mt], bh[nt]);
#pragma unroll
        for (int mt = 0; mt < 4; mt++)
#pragma unroll
            for (int nt = 0; nt < 8; nt++) mma16(acc[mt][nt], ah[mt], bl[nt]);
#pragma unroll
        for (int mt = 0; mt < 4; mt++)
#pragma unroll
            for (int nt = 0; nt < 8; nt++) mma16(acc[mt][nt], al[mt], bh[nt]);
        __syncthreads();
    }

#pragma unroll
    for (int mt = 0; mt < 4; mt++) {
        int t = mt * 16 + gid;
#pragma unroll
        for (int nt = 0; nt < 8; nt++) {
            int n = col0 + wn * 64 + nt * 8 + tig * 2;
            float b0 = w.x * be[e.x * H_DIM + n]     + w.y * be[e.y * H_DIM + n];
            float b1 = w.x * be[e.x * H_DIM + n + 1] + w.y * be[e.y * H_DIM + n + 1];
            if (t < S)
                *(float2*)(out + ((size_t)i * S + t) * H_DIM + n) =
                    make_float2(acc[mt][nt][0] + b0, acc[mt][nt][1] + b1);
            if (t + 8 < S)
                *(float2*)(out + ((size_t)i * S + t + 8) * H_DIM + n) =
                    make_float2(acc[mt][nt][2] + b0, acc[mt][nt][3] + b1);
        }
    }
}

// ---- MoE S=65 (bf16x3): block 80x128, 4 warps each 80x32 ------------------
__global__ __launch_bounds__(128, 2) void moe3_tc(
    const float* __restrict__ cls, const float* __restrict__ tok,
    const float* __restrict__ We, const float* __restrict__ be,
    const int2* __restrict__ eidx, const float2* __restrict__ ew,
    float* __restrict__ out)
{
    const int S = 65;
    __shared__ uint32_t AsH[80 * ASTRP], AsL[80 * ASTRP];
    __shared__ uint32_t BsH[8 * BSTRP], BsL[8 * BSTRP];

    const int i = blockIdx.z;
    const int col0 = blockIdx.x * 128;
    const int2 e = eidx[i];
    const float2 w = ew[i];
    const float* W0 = We + (size_t)e.x * H_DIM * H_DIM;
    const float* W1 = We + (size_t)e.y * H_DIM * H_DIM;

    const int tid = threadIdx.x;
    const int warp = tid >> 5, lane = tid & 31;
    const int wn = warp;
    const int gid = lane >> 2, tig = lane & 3;
    const int bk = tid >> 4;
    const int nc = (tid & 15) * 8;

    const float* rp = nullptr;
    if (tid < S)
        rp = (tid == 0) ? (cls + (size_t)i * H_DIM)
                        : (tok + ((size_t)i * (S - 1) + (tid - 1)) * H_DIM);

    float acc[5][4][4];
#pragma unroll
    for (int a = 0; a < 5; a++)
#pragma unroll
        for (int b = 0; b < 4; b++)
#pragma unroll
            for (int c = 0; c < 4; c++) acc[a][b][c] = 0.f;

    for (int kb = 0; kb < H_DIM / 16; kb++) {
        const int k0 = kb * 16;
        if (tid < 80) {
#pragma unroll
            for (int q = 0; q < 4; q++) {
                float4 v = make_float4(0.f, 0.f, 0.f, 0.f);
                if (rp) v = *(const float4*)(rp + k0 + q * 4);
                uint32_t h0, l0, h1, l1;
                split_bf16x2(v.x, v.y, h0, l0);
                split_bf16x2(v.z, v.w, h1, l1);
                *(uint2*)&AsH[tid * ASTRP + q * 2] = make_uint2(h0, h1);
                *(uint2*)&AsL[tid * ASTRP + q * 2] = make_uint2(l0, l1);
            }
        }
        {
            size_t o0 = (size_t)(k0 + 2 * bk) * H_DIM + col0 + nc;
#pragma unroll
            for (int q = 0; q < 2; q++) {
                float4 a0 = *(const float4*)(W0 + o0 + q * 4);
                float4 b0 = *(const float4*)(W1 + o0 + q * 4);
                float4 a1 = *(const float4*)(W0 + o0 + H_DIM + q * 4);
                float4 b1 = *(const float4*)(W1 + o0 + H_DIM + q * 4);
                float4 r0 = make_float4(w.x * a0.x + w.y * b0.x, w.x * a0.y + w.y * b0.y,
                                        w.x * a0.z + w.y * b0.z, w.x * a0.w + w.y * b0.w);
                float4 r1 = make_float4(w.x * a1.x + w.y * b1.x, w.x * a1.y + w.y * b1.y,
                                        w.x * a1.z + w.y * b1.z, w.x * a1.w + w.y * b1.w);
                uint4 h, l;
                splitB4(r0, r1, h, l);
                *(uint4*)&BsH[bk * BSTRP + nc + q * 4] = h;
                *(uint4*)&BsL[bk * BSTRP + nc + q * 4] = l;
            }
        }
        __syncthreads();

        uint32_t ah[5][4], al[5][4], bh[4][2], bl[4][2];
#pragma unroll
        for (int mt = 0; mt < 5; mt++) {
            int r = (mt * 16 + gid) * ASTRP;
            ah[mt][0] = AsH[r + tig];     ah[mt][1] = AsH[r + 8 * ASTRP + tig];
            ah[mt][2] = AsH[r + tig + 4]; ah[mt][3] = AsH[r + 8 * ASTRP + tig + 4];
            al[mt][0] = AsL[r + tig];     al[mt][1] = AsL[r + 8 * ASTRP + tig];
            al[mt][2] = AsL[r + tig + 4]; al[mt][3] = AsL[r + 8 * ASTRP + tig + 4];
        }
#pragma unroll
        for (int nt = 0; nt < 4; nt++) {
            int c = wn * 32 + nt * 8 + gid;
            bh[nt][0] = BsH[tig * BSTRP + c]; bh[nt][1] = BsH[(tig + 4) * BSTRP + c];
            bl[nt][0] = BsL[tig * BSTRP + c]; bl[nt][1] = BsL[(tig + 4) * BSTRP + c];
        }
#pragma unroll
        for (int mt = 0; mt < 5; mt++)
#pragma unroll
            for (int nt = 0; nt < 4; nt++) mma16(acc[mt][nt], ah[mt], bh[nt]);
#pragma unroll
        for (int mt = 0; mt < 5; mt++)
#pragma unroll
            for (int nt = 0; nt < 4; nt++) mma16(acc[mt][nt], ah[mt], bl[nt]);
#pragma unroll
        for (int mt = 0; mt < 5; mt++)
#pragma unroll
            for (int nt = 0; nt < 4; nt++) mma16(acc[mt][nt], al[mt], bh[nt]);
        __syncthreads();
    }

#pragma unroll
    for (int mt = 0; mt < 5; mt++) {
        int t = mt * 16 + gid;
#pragma unroll
        for (int nt = 0; nt < 4; nt++) {
            int n = col0 + wn * 32 + nt * 8 + tig * 2;
            float b0 = w.x * be[e.x * H_DIM + n]     + w.y * be[e.y * H_DIM + n];
            float b1 = w.x * be[e.x * H_DIM + n + 1] + w.y * be[e.y * H_DIM + n + 1];
            if (t < S)
                *(float2*)(out + ((size_t)i * S + t) * H_DIM + n) =
                    make_float2(acc[mt][nt][0] + b0, acc[mt][nt][1] + b1);
            if (t + 8 < S)
                *(float2*)(out + ((size_t)i * S + t + 8) * H_DIM + n) =
                    make_float2(acc[mt][nt][2] + b0, acc[mt][nt][3] + b1);
        }
    }
}

// ------ router weight folding + projection-weight pre-split (one kernel) ----
__global__ void combine_w_kernel(const float* __restrict__ Wt, const float* __restrict__ Wi,
                                 const float* __restrict__ Wr,
                                 float* __restrict__ WcT, float* __restrict__ WcI,
                                 uint32_t* __restrict__ Wh, uint32_t* __restrict__ Wl)
{
    int idx = blockIdx.x * blockDim.x + threadIdx.x;
    if (idx < D_IN * N_EXP) {
        int k = idx >> 3, e = idx & 7;
        float st = 0.f, si = 0.f;
        for (int h = 0; h < H_DIM; h++) {
            float wr = Wr[h * N_EXP + e];
            st += Wt[(size_t)k * H_DIM + h] * wr;
            si += Wi[(size_t)k * H_DIM + h] * wr;
        }
        WcT[idx] = st;
        WcI[idx] = si;
    }
    if (idx < 2 * WSP_SZ) {
        int which = idx / WSP_SZ;
        int rem = idx - which * WSP_SZ;
        int p = rem / H_DIM, n = rem - (rem / H_DIM) * H_DIM;
        const float* W = which ? Wi : Wt;
        float a = W[(size_t)(2 * p) * H_DIM + n];
        float b = W[(size_t)(2 * p + 1) * H_DIM + n];
        uint32_t h, l;
        split_bf16x2(a, b, h, l);
        Wh[idx] = h;
        Wl[idx] = l;
    }
}

__global__ void bterm_kernel(const float* __restrict__ bt, const float* __restrict__ bi,
                             const float* __restrict__ Wr, const float* __restrict__ br,
                             float* __restrict__ bterm)
{
    int e = threadIdx.x;
    if (e < N_EXP) {
        float sA = 0.f, sB = 0.f;
        for (int h = 0; h < H_DIM; h++) {
            float wr = Wr[h * N_EXP + e];
            sA += (bi[h] + 64.f * bt[h]) * wr;
            sB += (bt[h] + 49.f * bi[h]) * wr;
        }
        bterm[e]         = sA / 65.f + br[e];
        bterm[N_EXP + e] = sB / 50.f + br[e];
    }
}

// ------------- cross attention: tokens resident in dynamic smem -------------
__global__ __launch_bounds__(256) void cross_kernel(
    const float* __restrict__ moe_out, int S, float* __restrict__ ctx)
{
    extern __shared__ float tokbuf[];
    __shared__ float prob[64];
    const int i = blockIdx.x;
    const int tid = threadIdx.x;
    const float* base = moe_out + (size_t)i * S * H_DIM;

    {
        const float4* src = (const float4*)base;
        float4* dst = (float4*)tokbuf;
        const int n4 = S * (H_DIM / 4);
        for (int idx = tid; idx < n4; idx += 256) dst[idx] = src[idx];
    }
    __syncthreads();

    const int nt = S - 1;
    const int warp = tid >> 5, lane = tid & 31;
    for (int s = warp; s < nt; s += 8) {
        const float4* tr = (const float4*)(tokbuf + (s + 1) * H_DIM);
        const float4* cl = (const float4*)tokbuf;
        float p = 0.f;
#pragma unroll
        for (int q = 0; q < 4; q++) {
            float4 a = cl[lane + 32 * q];
            float4 b = tr[lane + 32 * q];
            p += a.x * b.x + a.y * b.y + a.z * b.z + a.w * b.w;
        }
#pragma unroll
        for (int o = 16; o; o >>= 1) p += __shfl_down_sync(0xffffffffu, p, o);
        if (lane == 0) prob[s] = p;
    }
    __syncthreads();

    if (tid == 0) {
        float mx = -1e30f;
        for (int s = 0; s < nt; s++) mx = fmaxf(mx, prob[s]);
        float sum = 0.f;
        for (int s = 0; s < nt; s++) { float e = expf(prob[s] - mx); prob[s] = e; sum += e; }
        float inv = 1.0f / sum;
        for (int s = 0; s < nt; s++) prob[s] *= inv;
    }
    __syncthreads();

    float2 acc = make_float2(0.f, 0.f);
    const float2* b2 = (const float2*)(tokbuf + H_DIM) + tid;
#pragma unroll 4
    for (int s = 0; s < nt; s++) {
        float2 v = b2[(size_t)s * (H_DIM / 2)];
        float pw = prob[s];
        acc.x += pw * v.x; acc.y += pw * v.y;
    }
    ((float2*)(ctx + (size_t)i * H_DIM))[tid] = acc;
}

// --------------------------- gate + residual + LN ---------------------------
__global__ __launch_bounds__(256) void gate_ln_kernel(
    const float* __restrict__ ori, const float* __restrict__ ctx,
    const float* __restrict__ Wg, const float* __restrict__ bg,
    const float* __restrict__ ls, const float* __restrict__ lb,
    float* __restrict__ out, int gate_from_ctx)
{
    const int i = blockIdx.x;
    __shared__ float v[H_DIM];
    __shared__ float red[256];
    const int tid = threadIdx.x;
    const float* orow = ori + (size_t)i * H_DIM;
    const float* crow = ctx + (size_t)i * H_DIM;

    float p = 0.f;
    for (int c = tid; c < H_DIM; c += 256) {
        float gs = gate_from_ctx ? crow[c] : orow[c];
        p += gs * Wg[c];
    }
    red[tid] = p; __syncthreads();
    for (int o = 128; o; o >>= 1) { if (tid < o) red[tid] += red[tid + o]; __syncthreads(); }
    float gate = tanhf(red[0] + bg[0]);
    __syncthreads();

    float sum = 0.f;
    for (int c = tid; c < H_DIM; c += 256) {
        float val = orow[c] * gate + crow[c];
        v[c] = val; sum += val;
    }
    red[tid] = sum; __syncthreads();
    for (int o = 128; o; o >>= 1) { if (tid < o) red[tid] += red[tid + o]; __syncthreads(); }
    float mean = red[0] / (float)H_DIM;
    __syncthreads();

    float var = 0.f;
    for (int c = tid; c < H_DIM; c += 256) { float d = v[c] - mean; var += d * d; }
    red[tid] = var; __syncthreads();
    for (int o = 128; o; o >>= 1) { if (tid < o) red[tid] += red[tid + o]; __syncthreads(); }
    float rstd = rsqrtf(red[0] / (float)H_DIM + 1e-5f);

    for (int c = tid; c < H_DIM; c += 256)
        out[(size_t)i * H_DIM + c] = (v[c] - mean) * rstd * ls[c] + lb[c];
}

// -------------------------------- final score -------------------------------
__global__ __launch_bounds__(256) void score_kernel(
    const float* __restrict__ mti, const float* __restrict__ eti,
    const float* __restrict__ mit, const float* __restrict__ eit,
    float* __restrict__ out)
{
    __shared__ float As[8][64];
    __shared__ float Bs[8][64];
    const int n0 = blockIdx.x * 64;
    const int b0 = blockIdx.y * 64;
    const int tid = threadIdx.x;
    const int tx = tid & 15, ty = tid >> 4;
    const int lrow = tid >> 2, lcol = (tid & 3) * 2;

    float acc[4][4];
#pragma unroll
    for (int q = 0; q < 4; q++)
#pragma unroll
        for (int r = 0; r < 4; r++) acc[q][r] = 0.f;

#pragma unroll
    for (int pass = 0; pass < 2; pass++) {
        const float* A = pass ? mit : mti;
        const float* B = pass ? eit : eti;
        for (int k0 = 0; k0 < H_DIM; k0 += 8) {
            float2 av = *(const float2*)(A + (size_t)(b0 + lrow) * H_DIM + k0 + lcol);
            As[lcol][lrow] = av.x; As[lcol + 1][lrow] = av.y;
            float2 bv = *(const float2*)(B + (size_t)(n0 + lrow) * H_DIM + k0 + lcol);
            Bs[lcol][lrow] = bv.x; Bs[lcol + 1][lrow] = bv.y;
            __syncthreads();
#pragma unroll
            for (int k = 0; k < 8; k++) {
                float a[4], b[4];
#pragma unroll
                for (int q = 0; q < 4; q++) a[q] = As[k][ty * 4 + q];
#pragma unroll
                for (int q = 0; q < 4; q++) b[q] = Bs[k][tx * 4 + q];
#pragma unroll
                for (int q = 0; q < 4; q++)
#pragma unroll
                    for (int r = 0; r < 4; r++) acc[q][r] += a[q] * b[r];
            }
            __syncthreads();
        }
    }
#pragma unroll
    for (int q = 0; q < 4; q++)
#pragma unroll
        for (int r = 0; r < 4; r++)
            out[(size_t)(b0 + ty * 4 + q) * N_ENT + (n0 + tx * 4 + r)] = 0.5f * acc[q][r];
}

// ---------------------------------- launch ----------------------------------
extern "C" void kernel_launch(void* const* d_in, const int* in_sizes, int n_in,
                              void* d_out, int out_size)
{
    const float* etc_in = (const float*)d_in[0];
    const float* ett_in = (const float*)d_in[1];
    const float* mtc_in = (const float*)d_in[2];
    const float* mtt_in = (const float*)d_in[3];
    const float* eic_in = (const float*)d_in[4];
    const float* eit_in = (const float*)d_in[5];
    const float* mic_in = (const float*)d_in[6];
    const float* mit_in = (const float*)d_in[7];
    const float* W_text = (const float*)d_in[8];
    const float* b_text = (const float*)d_in[9];
    const float* W_img  = (const float*)d_in[10];
    const float* b_img  = (const float*)d_in[11];
    const float* W_gate = (const float*)d_in[12];
    const float* b_gate = (const float*)d_in[13];
    const float* ln_s   = (const float*)d_in[14];
    const float* ln_b   = (const float*)d_in[15];
    const float* W_rout = (const float*)d_in[16];
    const float* b_rout = (const float*)d_in[17];
    const float* W_exp  = (const float*)d_in[18];
    const float* b_exp  = (const float*)d_in[19];
    float* out = (float*)d_out;

    float *p_etc, *p_eic, *p_mtc, *p_mic, *p_ett, *p_eit, *p_mtt, *p_mit;
    float *p_etim, *p_mtim, *p_eitm, *p_mitm;
    float *p_ctx0, *p_ctx1, *p_ctx2, *p_ctx3;
    float *p_feti, *p_fmti, *p_feit, *p_fmit;
    float *p_wct, *p_wci, *p_bt;
    uint32_t *p_wh, *p_wl;
    int2* p_eidx; float2* p_ew;
    cudaGetSymbolAddress((void**)&p_etc, g_etc);
    cudaGetSymbolAddress((void**)&p_eic, g_eic);
    cudaGetSymbolAddress((void**)&p_mtc, g_mtc);
    cudaGetSymbolAddress((void**)&p_mic, g_mic);
    cudaGetSymbolAddress((void**)&p_ett, g_ett);
    cudaGetSymbolAddress((void**)&p_eit, g_eit);
    cudaGetSymbolAddress((void**)&p_mtt, g_mtt);
    cudaGetSymbolAddress((void**)&p_mit, g_mit);
    cudaGetSymbolAddress((void**)&p_etim, g_eti_m);
    cudaGetSymbolAddress((void**)&p_mtim, g_mti_m);
    cudaGetSymbolAddress((void**)&p_eitm, g_eit_m);
    cudaGetSymbolAddress((void**)&p_mitm, g_mit_m);
    cudaGetSymbolAddress((void**)&p_ctx0, g_ctx0);
    cudaGetSymbolAddress((void**)&p_ctx1, g_ctx1);
    cudaGetSymbolAddress((void**)&p_ctx2, g_ctx2);
    cudaGetSymbolAddress((void**)&p_ctx3, g_ctx3);
    cudaGetSymbolAddress((void**)&p_feti, g_fe_ti);
    cudaGetSymbolAddress((void**)&p_fmti, g_fm_ti);
    cudaGetSymbolAddress((void**)&p_feit, g_fe_it);
    cudaGetSymbolAddress((void**)&p_fmit, g_fm_it);
    cudaGetSymbolAddress((void**)&p_wct, g_wc_text);
    cudaGetSymbolAddress((void**)&p_wci, g_wc_img);
    cudaGetSymbolAddress((void**)&p_bt, g_bterm);
    cudaGetSymbolAddress((void**)&p_wh, g_wsp_h);
    cudaGetSymbolAddress((void**)&p_wl, g_wsp_l);
    cudaGetSymbolAddress((void**)&p_eidx, g_eidx);
    cudaGetSymbolAddress((void**)&p_ew,   g_ew);

    const int CROSS_SMEM = 65 * H_DIM * 4;
    cudaFuncSetAttribute(cross_kernel, cudaFuncAttributeMaxDynamicSharedMemorySize, CROSS_SMEM);

    dim3 blk(256);
    dim3 blkg(128);

    // 1: prep (router fold + proj weight pre-split)
    combine_w_kernel<<<(2 * WSP_SZ + 255) / 256, blk>>>(W_text, W_img, W_rout,
                                                        p_wct, p_wci, p_wh, p_wl);
    // 2: bias terms
    bterm_kernel<<<1, 32>>>(b_text, b_img, W_rout, b_rout, p_bt);

    // 3: stage-1 mega kernel — all routers + all projections, overlapped
    stage1_mega<<<MEGA_GRID, blkg>>>(
        etc_in, ett_in, mtc_in, mtt_in, eic_in, eit_in, mic_in, mit_in,
        p_wh, p_wl, b_text, b_img,
        p_wct, p_wci, p_bt,
        p_etc, p_ett, p_mtc, p_mtt, p_eic, p_eit, p_mic, p_mit,
        p_eidx, p_ew);

    // MoE GEMMs (combined expert pair, bf16x3)
    moe2_tc<<<dim3(2, 1, N_ENT), blkg>>>(p_etc, p_eit, W_exp, b_exp,
                                         p_eidx + 0 * N_ENT, p_ew + 0 * N_ENT, p_etim);
    moe2_tc<<<dim3(2, 1, BATCH), blkg>>>(p_mtc, p_mit, W_exp, b_exp,
                                         p_eidx + 1 * N_ENT, p_ew + 1 * N_ENT, p_mtim);
    moe3_tc<<<dim3(4, 1, N_ENT), blkg>>>(p_eic, p_ett, W_exp, b_exp,
                                         p_eidx + 2 * N_ENT, p_ew + 2 * N_ENT, p_eitm);
    moe3_tc<<<dim3(4, 1, BATCH), blkg>>>(p_mic, p_mtt, W_exp, b_exp,
                                         p_eidx + 3 * N_ENT, p_ew + 3 * N_ENT, p_mitm);

    // cross attention (tokens smem-resident)
    cross_kernel<<<N_ENT, blk, 50 * H_DIM * 4>>>(p_etim, 50, p_ctx0);
    cross_kernel<<<BATCH, blk, 50 * H_DIM * 4>>>(p_mtim, 50, p_ctx1);
    cross_kernel<<<N_ENT, blk, 65 * H_DIM * 4>>>(p_eitm, 65, p_ctx2);
    cross_kernel<<<BATCH, blk, 65 * H_DIM * 4>>>(p_mitm, 65, p_ctx3);

    // gate + residual + LN
    gate_ln_kernel<<<N_ENT, blk>>>(p_etc, p_ctx0, W_gate, b_gate, ln_s, ln_b, p_feti, 1);
    gate_ln_kernel<<<BATCH, blk>>>(p_mtc, p_ctx1, W_gate, b_gate, ln_s, ln_b, p_fmti, 0);
    gate_ln_kernel<<<N_ENT, blk>>>(p_eic, p_ctx2, W_gate, b_gate, ln_s, ln_b, p_feit, 1);
    gate_ln_kernel<<<BATCH, blk>>>(p_mic, p_ctx3, W_gate, b_gate, ln_s, ln_b, p_fmit, 0);

    // final score
    score_kernel<<<dim3(N_ENT / 64, BATCH / 64), blk>>>(p_fmti, p_feti, p_fmit, p_feit, out);
}